// round 11
// baseline (speedup 1.0000x reference)
#include <cuda_runtime.h>
#include <cuda_fp16.h>
#include <cstdint>
#include <math.h>

#define Bz  4
#define Tt  1024
#define Cc  1024
#define Hh  16
#define Dd  64
#define FFF 4096
#define MM  (Bz*Tt)           // 4096
#define NHEADS (Bz*Hh)        // 64

// ---------------- scratch (device globals) ----------------
__device__ float  g_x   [MM*Cc];                 // fp32 residual stream
__device__ __half h_ln  [MM*Cc];
__device__ __half h_enc [MM*Cc];
__device__ __half h_wqkv[Cc*Hh*3*Dd];
__device__ __half h_cwq [Cc*Hh*Dd];
__device__ __half h_cwkv[Cc*Hh*2*Dd];
__device__ __half h_wproj[Cc*Cc];
__device__ __half h_cwproj[Cc*Cc];
__device__ __half h_ff1w1[Cc*FFF];
__device__ __half h_ff1w2[FFF*Cc];
__device__ __half h_ff2w1[Cc*FFF];
__device__ __half h_ff2w2[FFF*Cc];
__device__ __half h_y   [MM*Hh*3*Dd];            // self-attn qkv packed
__device__ __half h_cq  [MM*Cc];                 // cross-attn Q
__device__ __half h_kv  [MM*Hh*2*Dd];            // cross-attn K|V packed
__device__ __half h_m   [MM*Cc];                 // merged attention out
__device__ __half h_ff  [MM*FFF];

// ---------------- streams/events (created once, pre-main) ----------------
static cudaStream_t g_s2, g_sb[3];
static cudaEvent_t  g_ev1, g_ev2, g_ev3, g_evb[3];
struct _StreamInit {
    _StreamInit() {
        cudaStreamCreateWithFlags(&g_s2, cudaStreamNonBlocking);
        for (int i = 0; i < 3; i++) cudaStreamCreateWithFlags(&g_sb[i], cudaStreamNonBlocking);
        cudaEventCreateWithFlags(&g_ev1, cudaEventDisableTiming);
        cudaEventCreateWithFlags(&g_ev2, cudaEventDisableTiming);
        cudaEventCreateWithFlags(&g_ev3, cudaEventDisableTiming);
        for (int i = 0; i < 3; i++) cudaEventCreateWithFlags(&g_evb[i], cudaEventDisableTiming);
    }
};
static _StreamInit _stream_init_once;

// ---------------- mma/ldmatrix/cp.async helpers ----------------
__device__ __forceinline__ uint32_t smem_u32(const void* p) {
    return (uint32_t)__cvta_generic_to_shared(p);
}
__device__ __forceinline__ void ldsm4(uint32_t& r0, uint32_t& r1, uint32_t& r2, uint32_t& r3, uint32_t a) {
    asm volatile("ldmatrix.sync.aligned.m8n8.x4.shared.b16 {%0,%1,%2,%3}, [%4];"
                 : "=r"(r0), "=r"(r1), "=r"(r2), "=r"(r3) : "r"(a));
}
__device__ __forceinline__ void ldsm4t(uint32_t& r0, uint32_t& r1, uint32_t& r2, uint32_t& r3, uint32_t a) {
    asm volatile("ldmatrix.sync.aligned.m8n8.x4.trans.shared.b16 {%0,%1,%2,%3}, [%4];"
                 : "=r"(r0), "=r"(r1), "=r"(r2), "=r"(r3) : "r"(a));
}
__device__ __forceinline__ void mma16816(float* c, uint32_t a0, uint32_t a1, uint32_t a2, uint32_t a3,
                                         uint32_t b0, uint32_t b1) {
    asm volatile("mma.sync.aligned.m16n8k16.row.col.f32.f16.f16.f32 "
                 "{%0,%1,%2,%3},{%4,%5,%6,%7},{%8,%9},{%0,%1,%2,%3};"
                 : "+f"(c[0]), "+f"(c[1]), "+f"(c[2]), "+f"(c[3])
                 : "r"(a0), "r"(a1), "r"(a2), "r"(a3), "r"(b0), "r"(b1));
}
__device__ __forceinline__ void cpa16(uint32_t dst, const void* src) {
    asm volatile("cp.async.cg.shared.global [%0], [%1], 16;" :: "r"(dst), "l"(src));
}
#define CP_COMMIT()  asm volatile("cp.async.commit_group;")
#define CP_WAIT(n)   asm volatile("cp.async.wait_group %0;" :: "n"(n) : "memory")

// ---------------- converts ----------------
__global__ void f2h_kernel(const float* __restrict__ src, __half* __restrict__ dst, int n4) {
    int i = blockIdx.x * blockDim.x + threadIdx.x;
    if (i >= n4) return;
    float4 v = ((const float4*)src)[i];
    __half2* o = (__half2*)dst + i * 2;
    o[0] = __floats2half2_rn(v.x, v.y);
    o[1] = __floats2half2_rn(v.z, v.w);
}
__global__ void pack_w_kernel(const float* __restrict__ W, __half* __restrict__ Wt, int J) {
    int i = blockIdx.x * blockDim.x + threadIdx.x;
    int J8 = J >> 3;
    int total8 = Hh * Cc * J8;
    if (i >= total8) return;
    int j8 = i % J8;
    int c = (i / J8) % Cc;
    int h = i / (J8 * Cc);
    const float4* src = (const float4*)(W + (size_t)(h * Cc + c) * J + j8 * 8);
    float4 v0 = src[0], v1 = src[1];
    __half2 o[4];
    o[0] = __floats2half2_rn(v0.x, v0.y); o[1] = __floats2half2_rn(v0.z, v0.w);
    o[2] = __floats2half2_rn(v1.x, v1.y); o[3] = __floats2half2_rn(v1.z, v1.w);
    *(uint4*)(Wt + (size_t)c * (Hh * J) + h * J + j8 * 8) = *(uint4*)o;
}

// ---------------- layernorm: warp-per-row ----------------
__global__ void __launch_bounds__(256) ln_kernel(const float* __restrict__ X,
                                                 const float* __restrict__ w,
                                                 const float* __restrict__ b,
                                                 __half* __restrict__ Y) {
    int warp = threadIdx.x >> 5, lane = threadIdx.x & 31;
    int row = blockIdx.x * 8 + warp;
    const float4* x4 = (const float4*)(X + (size_t)row * Cc);
    float4 v[8];
    float s = 0.f, sq = 0.f;
    #pragma unroll
    for (int i = 0; i < 8; i++) {
        v[i] = x4[lane + i * 32];
        s  += v[i].x + v[i].y + v[i].z + v[i].w;
        sq += v[i].x*v[i].x + v[i].y*v[i].y + v[i].z*v[i].z + v[i].w*v[i].w;
    }
    #pragma unroll
    for (int o = 16; o > 0; o >>= 1) {
        s  += __shfl_xor_sync(0xffffffffu, s,  o);
        sq += __shfl_xor_sync(0xffffffffu, sq, o);
    }
    float mu   = s / Cc;
    float rstd = rsqrtf(sq / Cc - mu * mu + 1e-5f);
    const float4* w4 = (const float4*)w;
    const float4* b4 = (const float4*)b;
    uint2* y = (uint2*)(Y + (size_t)row * Cc);
    #pragma unroll
    for (int i = 0; i < 8; i++) {
        float4 wv = w4[lane + i * 32];
        float4 bv = b4[lane + i * 32];
        __half2 o0 = __floats2half2_rn((v[i].x - mu) * rstd * wv.x + bv.x,
                                       (v[i].y - mu) * rstd * wv.y + bv.y);
        __half2 o1 = __floats2half2_rn((v[i].z - mu) * rstd * wv.z + bv.z,
                                       (v[i].w - mu) * rstd * wv.w + bv.w);
        uint2 pk;
        pk.x = *(uint32_t*)&o0;
        pk.y = *(uint32_t*)&o1;
        y[lane + i * 32] = pk;
    }
}

// ---------------- fp16 GEMM, 128x256 tile, 4-stage cp.async ring ----------------
// 8 warps = 2(m) x 4(n); warp tile 64x64. N % 256 == 0.
// C = A[M,K]@B[K,N] (+bias)(+relu)(+res). outH!=null -> fp16 out, else fp32 outF.
#define HG_STAGES 4
#define HG_AS (128*40)
#define HG_BS (32*264)
#define HG_SMEM (HG_STAGES*(HG_AS+HG_BS)*2)   // 108544 bytes

__global__ void __launch_bounds__(256, 1) hgemm_kernel(const __half* __restrict__ A,
                                                       const __half* __restrict__ B,
                                                       const float* __restrict__ bias,
                                                       const float* __restrict__ res,
                                                       float* __restrict__ outF,
                                                       __half* __restrict__ outH,
                                                       int M, int N, int K, int relu) {
    extern __shared__ __half hsm[];
    __half (*As)[128][40]  = (__half(*)[128][40])hsm;
    __half (*Bs)[32][264]  = (__half(*)[32][264])(hsm + HG_STAGES * HG_AS);
    int tid = threadIdx.x, lane = tid & 31, warp = tid >> 5;
    int wm = warp >> 2, wn = warp & 3;           // 2 x 4 warps
    int m0 = blockIdx.y * 128, n0 = blockIdx.x * 256;

    // hoisted per-thread global bases (A: two rows; B: four rows)
    const __half* Ag0 = A + (size_t)(m0 + (tid >> 2)) * K + (tid & 3) * 8;
    const __half* Ag1 = A + (size_t)(m0 + ((tid + 256) >> 2)) * K + (tid & 3) * 8;
    const __half* Bg[4];
    #pragma unroll
    for (int j = 0; j < 4; j++) {
        int idx = tid + j * 256;
        Bg[j] = B + (size_t)(idx >> 5) * N + n0 + (idx & 31) * 8;
    }

    float acc[4][8][4] = {};

    auto load_stage = [&](int k0, int st) {
        cpa16(smem_u32(&As[st][tid >> 2][(tid & 3) * 8]), Ag0 + k0);
        cpa16(smem_u32(&As[st][(tid + 256) >> 2][(tid & 3) * 8]), Ag1 + k0);
        #pragma unroll
        for (int j = 0; j < 4; j++) {
            int idx = tid + j * 256;
            cpa16(smem_u32(&Bs[st][idx >> 5][(idx & 31) * 8]), Bg[j] + (size_t)k0 * N);
        }
    };

    int nIter = K >> 5;
    load_stage(0, 0); CP_COMMIT();
    load_stage(32, 1); CP_COMMIT();

    for (int it = 0; it < nIter; it++) {
        if (it + 2 < nIter) load_stage((it + 2) << 5, (it + 2) & 3);
        CP_COMMIT();
        CP_WAIT(2);
        __syncthreads();
        int st = it & 3;
        #pragma unroll
        for (int kk = 0; kk < 32; kk += 16) {
            uint32_t a[4][4];
            #pragma unroll
            for (int mi = 0; mi < 4; mi++)
                ldsm4(a[mi][0], a[mi][1], a[mi][2], a[mi][3],
                      smem_u32(&As[st][wm * 64 + mi * 16 + (lane & 15)][kk + (lane >> 4) * 8]));
            #pragma unroll
            for (int n4 = 0; n4 < 4; n4++) {
                uint32_t b0, b1, b2, b3;
                ldsm4t(b0, b1, b2, b3,
                       smem_u32(&Bs[st][kk + (lane & 15)][wn * 64 + n4 * 16 + (lane >> 4) * 8]));
                #pragma unroll
                for (int mi = 0; mi < 4; mi++) {
                    mma16816(acc[mi][n4 * 2],     a[mi][0], a[mi][1], a[mi][2], a[mi][3], b0, b1);
                    mma16816(acc[mi][n4 * 2 + 1], a[mi][0], a[mi][1], a[mi][2], a[mi][3], b2, b3);
                }
            }
        }
    }

    #pragma unroll
    for (int mi = 0; mi < 4; mi++) {
        #pragma unroll
        for (int ni = 0; ni < 8; ni++) {
            int col = n0 + wn * 64 + ni * 8 + (lane & 3) * 2;
            #pragma unroll
            for (int r = 0; r < 2; r++) {
                int row = m0 + wm * 64 + mi * 16 + (lane >> 2) + r * 8;
                float v0 = acc[mi][ni][r * 2], v1 = acc[mi][ni][r * 2 + 1];
                if (bias) { v0 += bias[col]; v1 += bias[col + 1]; }
                if (relu) { v0 = fmaxf(v0, 0.f); v1 = fmaxf(v1, 0.f); }
                size_t idx = (size_t)row * N + col;
                if (res) { v0 += res[idx]; v1 += res[idx + 1]; }
                if (outH) {
                    *(__half2*)&outH[idx] = __floats2half2_rn(v0, v1);
                } else {
                    *(float2*)&outF[idx] = make_float2(v0, v1);
                }
            }
        }
    }
}

// ---------------- fused flash attention, 4-stage cp.async K/V ring ----------------
#define FL_QS (128*72)
#define FL_KS (64*72)
#define FL_SMEM ((FL_QS + 8*FL_KS)*2)    // 92160 bytes

__global__ void __launch_bounds__(256, 2) flash_kernel(const __half* __restrict__ Q,
                                                       const __half* __restrict__ Kp,
                                                       const __half* __restrict__ Vp,
                                                       __half* __restrict__ Mg,
                                                       int strideQ, int pitchQ,
                                                       int strideKV, int pitchKV, int causal) {
    extern __shared__ __half fsm[];
    __half (*Qs)[72] = (__half(*)[72])fsm;
    __half (*Ks)[64][72] = (__half(*)[64][72])(fsm + FL_QS);
    __half (*Vs)[64][72] = (__half(*)[64][72])(fsm + FL_QS + 4 * FL_KS);
    int tid = threadIdx.x, lane = tid & 31, w = tid >> 5;
    int h = blockIdx.y;
    int t0 = (gridDim.x - 1 - blockIdx.x) * 128;
    const __half* Qb = Q  + h * pitchQ;
    const __half* Kb = Kp + h * pitchKV;
    const __half* Vb = Vp + h * pitchKV;

    auto load_kv = [&](int s0, int st) {
        #pragma unroll
        for (int j = 0; j < 2; j++) {
            int idx = tid + j * 256;
            int row = idx >> 3, col = (idx & 7) * 8;
            cpa16(smem_u32(&Ks[st][row][col]), Kb + (size_t)(s0 + row) * strideKV + col);
            cpa16(smem_u32(&Vs[st][row][col]), Vb + (size_t)(s0 + row) * strideKV + col);
        }
    };

    int sEnd = causal ? (t0 + 128) : Tt;
    int nT = sEnd >> 6;
    load_kv(0, 0); CP_COMMIT();
    if (nT > 1) load_kv(64, 1);
    CP_COMMIT();

    const __half2 sc = __float2half2_rn(0.125f);
    #pragma unroll
    for (int j = 0; j < 4; j++) {
        int idx = tid + j * 256;
        int row = idx >> 3, col = (idx & 7) * 8;
        uint4 v = *(const uint4*)(Qb + (size_t)(t0 + row) * strideQ + col);
        __half2* h2 = (__half2*)&v;
        #pragma unroll
        for (int q = 0; q < 4; q++) h2[q] = __hmul2(h2[q], sc);
        *(uint4*)&Qs[row][col] = v;
    }
    __syncthreads();

    uint32_t qf[4][4];
    #pragma unroll
    for (int kk = 0; kk < 4; kk++)
        ldsm4(qf[kk][0], qf[kk][1], qf[kk][2], qf[kk][3],
              smem_u32(&Qs[w * 16 + (lane & 15)][kk * 16 + (lane >> 4) * 8]));

    float m_[2] = {-1e30f, -1e30f}, l_[2] = {0.f, 0.f};
    float acc[8][4] = {};

    for (int i = 0; i < nT; i++) {
        if (i + 2 < nT) load_kv((i + 2) << 6, (i + 2) & 3);
        CP_COMMIT();
        CP_WAIT(2);
        __syncthreads();
        int st = i & 3;
        int s0 = i << 6;

        float sacc[8][4] = {};
        #pragma unroll
        for (int kk = 0; kk < 4; kk++) {
            #pragma unroll
            for (int sg = 0; sg < 4; sg++) {
                uint32_t b0, b1, b2, b3;
                ldsm4(b0, b1, b2, b3,
                      smem_u32(&Ks[st][sg * 16 + (lane & 7) + ((lane >> 4) << 3)][kk * 16 + ((lane >> 3) & 1) * 8]));
                mma16816(sacc[sg * 2],     qf[kk][0], qf[kk][1], qf[kk][2], qf[kk][3], b0, b1);
                mma16816(sacc[sg * 2 + 1], qf[kk][0], qf[kk][1], qf[kk][2], qf[kk][3], b2, b3);
            }
        }

        if (causal && s0 + 63 > t0 + w * 16) {
            int tr0 = t0 + w * 16 + (lane >> 2);
            int tr1 = tr0 + 8;
            #pragma unroll
            for (int ni = 0; ni < 8; ni++) {
                int s = s0 + ni * 8 + (lane & 3) * 2;
                if (s > tr0)     sacc[ni][0] = -1e30f;
                if (s + 1 > tr0) sacc[ni][1] = -1e30f;
                if (s > tr1)     sacc[ni][2] = -1e30f;
                if (s + 1 > tr1) sacc[ni][3] = -1e30f;
            }
        }

        __half2 ph[8][2];
        #pragma unroll
        for (int r = 0; r < 2; r++) {
            float rm = -1e30f;
            #pragma unroll
            for (int ni = 0; ni < 8; ni++)
                rm = fmaxf(rm, fmaxf(sacc[ni][r * 2], sacc[ni][r * 2 + 1]));
            rm = fmaxf(rm, __shfl_xor_sync(0xffffffffu, rm, 1));
            rm = fmaxf(rm, __shfl_xor_sync(0xffffffffu, rm, 2));
            float mn  = fmaxf(m_[r], rm);
            float fac = __expf(m_[r] - mn);
            float ls = 0.f;
            #pragma unroll
            for (int ni = 0; ni < 8; ni++) {
                float e0 = __expf(sacc[ni][r * 2]     - mn);
                float e1 = __expf(sacc[ni][r * 2 + 1] - mn);
                ls += e0 + e1;
                ph[ni][r] = __floats2half2_rn(e0, e1);
            }
            ls += __shfl_xor_sync(0xffffffffu, ls, 1);
            ls += __shfl_xor_sync(0xffffffffu, ls, 2);
            l_[r] = l_[r] * fac + ls;
            m_[r] = mn;
            #pragma unroll
            for (int ni = 0; ni < 8; ni++) { acc[ni][r * 2] *= fac; acc[ni][r * 2 + 1] *= fac; }
        }

        #pragma unroll
        for (int kk = 0; kk < 4; kk++) {
            uint32_t a0 = *(uint32_t*)&ph[2 * kk][0];
            uint32_t a1 = *(uint32_t*)&ph[2 * kk][1];
            uint32_t a2 = *(uint32_t*)&ph[2 * kk + 1][0];
            uint32_t a3 = *(uint32_t*)&ph[2 * kk + 1][1];
            #pragma unroll
            for (int n2 = 0; n2 < 4; n2++) {
                uint32_t b0, b1, b2, b3;
                ldsm4t(b0, b1, b2, b3,
                       smem_u32(&Vs[st][kk * 16 + (lane & 15)][n2 * 16 + (lane >> 4) * 8]));
                mma16816(acc[n2 * 2],     a0, a1, a2, a3, b0, b1);
                mma16816(acc[n2 * 2 + 1], a0, a1, a2, a3, b2, b3);
            }
        }
    }

    float inv0 = 1.f / l_[0], inv1 = 1.f / l_[1];
    #pragma unroll
    for (int ni = 0; ni < 8; ni++) {
        int d = ni * 8 + (lane & 3) * 2;
        int t = t0 + w * 16 + (lane >> 2);
        *(__half2*)&Mg[(size_t)t * Cc + h * Dd + d] =
            __floats2half2_rn(acc[ni][0] * inv0, acc[ni][1] * inv0);
        *(__half2*)&Mg[(size_t)(t + 8) * Cc + h * Dd + d] =
            __floats2half2_rn(acc[ni][2] * inv1, acc[ni][3] * inv1);
    }
}

// ======================================================================
extern "C" void kernel_launch(void* const* d_in, const int* in_sizes, int n_in,
                              void* d_out, int out_size) {
    const float* x       = (const float*)d_in[0];
    const float* enc     = (const float*)d_in[1];
    const float* w_qkv   = (const float*)d_in[2];
    const float* w_proj  = (const float*)d_in[3];
    const float* b_proj  = (const float*)d_in[4];
    const float* cw_q    = (const float*)d_in[5];
    const float* cw_kv   = (const float*)d_in[6];
    const float* cw_proj = (const float*)d_in[7];
    const float* cb_proj = (const float*)d_in[8];
    const float* ff1_w1  = (const float*)d_in[9];
    const float* ff1_b1  = (const float*)d_in[10];
    const float* ff1_w2  = (const float*)d_in[11];
    const float* ff1_b2  = (const float*)d_in[12];
    const float* ff2_w1  = (const float*)d_in[13];
    const float* ff2_b1  = (const float*)d_in[14];
    const float* ff2_w2  = (const float*)d_in[15];
    const float* ff2_b2  = (const float*)d_in[16];
    const float* ln1_w = (const float*)d_in[17]; const float* ln1_b = (const float*)d_in[18];
    const float* ln2_w = (const float*)d_in[19]; const float* ln2_b = (const float*)d_in[20];
    const float* ln3_w = (const float*)d_in[21]; const float* ln3_b = (const float*)d_in[22];
    const float* ln4_w = (const float*)d_in[23]; const float* ln4_b = (const float*)d_in[24];

    float *px;
    __half *pln, *penc, *pwqkv, *pcwq, *pcwkv, *pwproj, *pcwproj;
    __half *pf11, *pf12, *pf21, *pf22;
    __half *py, *pcq, *pkv, *pm, *pff;
    cudaGetSymbolAddress((void**)&px,     g_x);
    cudaGetSymbolAddress((void**)&pln,    h_ln);
    cudaGetSymbolAddress((void**)&penc,   h_enc);
    cudaGetSymbolAddress((void**)&pwqkv,  h_wqkv);
    cudaGetSymbolAddress((void**)&pcwq,   h_cwq);
    cudaGetSymbolAddress((void**)&pcwkv,  h_cwkv);
    cudaGetSymbolAddress((void**)&pwproj, h_wproj);
    cudaGetSymbolAddress((void**)&pcwproj,h_cwproj);
    cudaGetSymbolAddress((void**)&pf11,   h_ff1w1);
    cudaGetSymbolAddress((void**)&pf12,   h_ff1w2);
    cudaGetSymbolAddress((void**)&pf21,   h_ff2w1);
    cudaGetSymbolAddress((void**)&pf22,   h_ff2w2);
    cudaGetSymbolAddress((void**)&py,     h_y);
    cudaGetSymbolAddress((void**)&pcq,    h_cq);
    cudaGetSymbolAddress((void**)&pkv,    h_kv);
    cudaGetSymbolAddress((void**)&pm,     h_m);
    cudaGetSymbolAddress((void**)&pff,    h_ff);

    cudaFuncSetAttribute(hgemm_kernel, cudaFuncAttributeMaxDynamicSharedMemorySize, HG_SMEM);
    cudaFuncSetAttribute(flash_kernel, cudaFuncAttributeMaxDynamicSharedMemorySize, FL_SMEM);

    auto cgrid = [](int n) { return (n + 255) / 256; };

    // ---- critical-path converts on the capture stream ----
    pack_w_kernel<<<cgrid(Hh*Cc*192/8), 256>>>(w_qkv, pwqkv, 192);
    cudaMemcpyAsync(px, x, (size_t)MM * Cc * sizeof(float), cudaMemcpyDeviceToDevice, 0);
    cudaEventRecord(g_ev1, 0);

    // ---- converts + cross-KV GEMM on side stream ----
    cudaStreamWaitEvent(g_s2, g_ev1, 0);
    pack_w_kernel<<<cgrid(Hh*Cc*64/8),  256, 0, g_s2>>>(cw_q,  pcwq,  64);
    pack_w_kernel<<<cgrid(Hh*Cc*128/8), 256, 0, g_s2>>>(cw_kv, pcwkv, 128);
    f2h_kernel<<<cgrid(Cc*Cc/4),  256, 0, g_s2>>>(w_proj,  pwproj,  Cc*Cc/4);
    f2h_kernel<<<cgrid(Cc*Cc/4),  256, 0, g_s2>>>(cw_proj, pcwproj, Cc*Cc/4);
    f2h_kernel<<<cgrid(Cc*FFF/4), 256, 0, g_s2>>>(ff1_w1, pf11, Cc*FFF/4);
    f2h_kernel<<<cgrid(FFF*Cc/4), 256, 0, g_s2>>>(ff1_w2, pf12, FFF*Cc/4);
    f2h_kernel<<<cgrid(Cc*FFF/4), 256, 0, g_s2>>>(ff2_w1, pf21, Cc*FFF/4);
    f2h_kernel<<<cgrid(FFF*Cc/4), 256, 0, g_s2>>>(ff2_w2, pf22, FFF*Cc/4);
    f2h_kernel<<<cgrid(MM*Cc/4),  256, 0, g_s2>>>(enc, penc, MM*Cc/4);
    cudaEventRecord(g_ev2, g_s2);            // weights ready
    hgemm_kernel<<<dim3(8, 32), 256, HG_SMEM, g_s2>>>(penc, pcwkv, nullptr, nullptr, nullptr, pkv, MM, 2048, Cc, 0);
    cudaEventRecord(g_ev3, g_s2);            // cross K/V ready

    // ---- per-batch pipelines on 4 streams ----
    auto run_batch = [&](int b, cudaStream_t st) {
        size_t oc = (size_t)b * Tt * Cc;
        float*  pxb  = px  + oc;
        __half* plnb = pln + oc;
        __half* pyb  = py  + (size_t)b * Tt * 3072;
        __half* pcqb = pcq + oc;
        __half* pkvb = pkv + (size_t)b * Tt * 2048;
        __half* pmb  = pm  + oc;
        __half* pffb = pff + (size_t)b * Tt * FFF;
        float*  poutb = (float*)d_out + oc;

        // 1) causal self-attention
        ln_kernel<<<Tt/8, 256, 0, st>>>(pxb, ln1_w, ln1_b, plnb);
        hgemm_kernel<<<dim3(12, 8), 256, HG_SMEM, st>>>(plnb, pwqkv, nullptr, nullptr, nullptr, pyb, Tt, 3072, Cc, 0);
        flash_kernel<<<dim3(8, Hh), 256, FL_SMEM, st>>>(pyb, pyb + 64, pyb + 128, pmb, 3072, 192, 3072, 192, 1);
        cudaStreamWaitEvent(st, g_ev2, 0);
        hgemm_kernel<<<dim3(4, 8), 256, HG_SMEM, st>>>(pmb, pwproj, b_proj, pxb, pxb, nullptr, Tt, Cc, Cc, 0);

        // 2) feed-forward 1
        ln_kernel<<<Tt/8, 256, 0, st>>>(pxb, ln2_w, ln2_b, plnb);
        hgemm_kernel<<<dim3(16, 8), 256, HG_SMEM, st>>>(plnb, pf11, ff1_b1, nullptr, nullptr, pffb, Tt, FFF, Cc, 1);
        hgemm_kernel<<<dim3(4, 8), 256, HG_SMEM, st>>>(pffb, pf12, ff1_b2, pxb, pxb, nullptr, Tt, Cc, FFF, 0);

        // 3) cross-attention
        ln_kernel<<<Tt/8, 256, 0, st>>>(pxb, ln3_w, ln3_b, plnb);
        hgemm_kernel<<<dim3(4, 8), 256, HG_SMEM, st>>>(plnb, pcwq, nullptr, nullptr, nullptr, pcqb, Tt, 1024, Cc, 0);
        cudaStreamWaitEvent(st, g_ev3, 0);
        flash_kernel<<<dim3(8, Hh), 256, FL_SMEM, st>>>(pcqb, pkvb, pkvb + 64, pmb, 1024, 64, 2048, 128, 0);
        hgemm_kernel<<<dim3(4, 8), 256, HG_SMEM, st>>>(pmb, pcwproj, cb_proj, pxb, pxb, nullptr, Tt, Cc, Cc, 0);

        // 4) feed-forward 2 -> d_out
        ln_kernel<<<Tt/8, 256, 0, st>>>(pxb, ln4_w, ln4_b, plnb);
        hgemm_kernel<<<dim3(16, 8), 256, HG_SMEM, st>>>(plnb, pf21, ff2_b1, nullptr, nullptr, pffb, Tt, FFF, Cc, 1);
        hgemm_kernel<<<dim3(4, 8), 256, HG_SMEM, st>>>(pffb, pf22, ff2_b2, pxb, poutb, nullptr, Tt, Cc, FFF, 0);
    };

    for (int i = 0; i < 3; i++) cudaStreamWaitEvent(g_sb[i], g_ev1, 0);
    run_batch(0, 0);
    for (int i = 0; i < 3; i++) run_batch(i + 1, g_sb[i]);

    for (int i = 0; i < 3; i++) {
        cudaEventRecord(g_evb[i], g_sb[i]);
        cudaStreamWaitEvent(0, g_evb[i], 0);
    }
    cudaStreamWaitEvent(0, g_ev3, 0);
}

// round 13
// speedup vs baseline: 1.0477x; 1.0477x over previous
#include <cuda_runtime.h>
#include <cuda_fp16.h>
#include <cstdint>
#include <math.h>

#define Bz  4
#define Tt  1024
#define Cc  1024
#define Hh  16
#define Dd  64
#define FFF 4096
#define MM  (Bz*Tt)           // 4096
#define NHEADS (Bz*Hh)        // 64

// ---------------- scratch (device globals) ----------------
__device__ float  g_x   [MM*Cc];                 // fp32 residual stream
__device__ __half h_ln  [MM*Cc];
__device__ __half h_enc [MM*Cc];
__device__ __half h_wqkv[Cc*Hh*3*Dd];
__device__ __half h_cwq [Cc*Hh*Dd];
__device__ __half h_cwkv[Cc*Hh*2*Dd];
__device__ __half h_wproj[Cc*Cc];
__device__ __half h_cwproj[Cc*Cc];
__device__ __half h_ff1w1[Cc*FFF];
__device__ __half h_ff1w2[FFF*Cc];
__device__ __half h_ff2w1[Cc*FFF];
__device__ __half h_ff2w2[FFF*Cc];
__device__ __half h_y   [MM*Hh*3*Dd];            // self-attn qkv packed
__device__ __half h_cq  [MM*Cc];                 // cross-attn Q
__device__ __half h_kv  [MM*Hh*2*Dd];            // cross-attn K|V packed
__device__ __half h_m   [MM*Cc];                 // merged attention out
__device__ __half h_ff  [MM*FFF];

// ---------------- streams/events (created once, pre-main) ----------------
static cudaStream_t g_s2, g_sb[3];
static cudaEvent_t  g_ev1, g_ev2, g_ev3, g_evb[3];
struct _StreamInit {
    _StreamInit() {
        cudaStreamCreateWithFlags(&g_s2, cudaStreamNonBlocking);
        for (int i = 0; i < 3; i++) cudaStreamCreateWithFlags(&g_sb[i], cudaStreamNonBlocking);
        cudaEventCreateWithFlags(&g_ev1, cudaEventDisableTiming);
        cudaEventCreateWithFlags(&g_ev2, cudaEventDisableTiming);
        cudaEventCreateWithFlags(&g_ev3, cudaEventDisableTiming);
        for (int i = 0; i < 3; i++) cudaEventCreateWithFlags(&g_evb[i], cudaEventDisableTiming);
    }
};
static _StreamInit _stream_init_once;

// ---------------- mma/ldmatrix/cp.async helpers ----------------
__device__ __forceinline__ uint32_t smem_u32(const void* p) {
    return (uint32_t)__cvta_generic_to_shared(p);
}
__device__ __forceinline__ void ldsm4(uint32_t& r0, uint32_t& r1, uint32_t& r2, uint32_t& r3, uint32_t a) {
    asm volatile("ldmatrix.sync.aligned.m8n8.x4.shared.b16 {%0,%1,%2,%3}, [%4];"
                 : "=r"(r0), "=r"(r1), "=r"(r2), "=r"(r3) : "r"(a));
}
__device__ __forceinline__ void ldsm4t(uint32_t& r0, uint32_t& r1, uint32_t& r2, uint32_t& r3, uint32_t a) {
    asm volatile("ldmatrix.sync.aligned.m8n8.x4.trans.shared.b16 {%0,%1,%2,%3}, [%4];"
                 : "=r"(r0), "=r"(r1), "=r"(r2), "=r"(r3) : "r"(a));
}
__device__ __forceinline__ void mma16816(float* c, uint32_t a0, uint32_t a1, uint32_t a2, uint32_t a3,
                                         uint32_t b0, uint32_t b1) {
    asm volatile("mma.sync.aligned.m16n8k16.row.col.f32.f16.f16.f32 "
                 "{%0,%1,%2,%3},{%4,%5,%6,%7},{%8,%9},{%0,%1,%2,%3};"
                 : "+f"(c[0]), "+f"(c[1]), "+f"(c[2]), "+f"(c[3])
                 : "r"(a0), "r"(a1), "r"(a2), "r"(a3), "r"(b0), "r"(b1));
}
__device__ __forceinline__ void cpa16(uint32_t dst, const void* src) {
    asm volatile("cp.async.cg.shared.global [%0], [%1], 16;" :: "r"(dst), "l"(src));
}
#define CP_COMMIT()  asm volatile("cp.async.commit_group;")
#define CP_WAIT(n)   asm volatile("cp.async.wait_group %0;" :: "n"(n) : "memory")

// ---------------- converts ----------------
__global__ void f2h_kernel(const float* __restrict__ src, __half* __restrict__ dst, int n4) {
    int i = blockIdx.x * blockDim.x + threadIdx.x;
    if (i >= n4) return;
    float4 v = ((const float4*)src)[i];
    __half2* o = (__half2*)dst + i * 2;
    o[0] = __floats2half2_rn(v.x, v.y);
    o[1] = __floats2half2_rn(v.z, v.w);
}
__global__ void pack_w_kernel(const float* __restrict__ W, __half* __restrict__ Wt, int J) {
    int i = blockIdx.x * blockDim.x + threadIdx.x;
    int J8 = J >> 3;
    int total8 = Hh * Cc * J8;
    if (i >= total8) return;
    int j8 = i % J8;
    int c = (i / J8) % Cc;
    int h = i / (J8 * Cc);
    const float4* src = (const float4*)(W + (size_t)(h * Cc + c) * J + j8 * 8);
    float4 v0 = src[0], v1 = src[1];
    __half2 o[4];
    o[0] = __floats2half2_rn(v0.x, v0.y); o[1] = __floats2half2_rn(v0.z, v0.w);
    o[2] = __floats2half2_rn(v1.x, v1.y); o[3] = __floats2half2_rn(v1.z, v1.w);
    *(uint4*)(Wt + (size_t)c * (Hh * J) + h * J + j8 * 8) = *(uint4*)o;
}

// ---------------- layernorm: warp-per-row ----------------
__global__ void __launch_bounds__(256) ln_kernel(const float* __restrict__ X,
                                                 const float* __restrict__ w,
                                                 const float* __restrict__ b,
                                                 __half* __restrict__ Y) {
    int warp = threadIdx.x >> 5, lane = threadIdx.x & 31;
    int row = blockIdx.x * 8 + warp;
    const float4* x4 = (const float4*)(X + (size_t)row * Cc);
    float4 v[8];
    float s = 0.f, sq = 0.f;
    #pragma unroll
    for (int i = 0; i < 8; i++) {
        v[i] = x4[lane + i * 32];
        s  += v[i].x + v[i].y + v[i].z + v[i].w;
        sq += v[i].x*v[i].x + v[i].y*v[i].y + v[i].z*v[i].z + v[i].w*v[i].w;
    }
    #pragma unroll
    for (int o = 16; o > 0; o >>= 1) {
        s  += __shfl_xor_sync(0xffffffffu, s,  o);
        sq += __shfl_xor_sync(0xffffffffu, sq, o);
    }
    float mu   = s / Cc;
    float rstd = rsqrtf(sq / Cc - mu * mu + 1e-5f);
    const float4* w4 = (const float4*)w;
    const float4* b4 = (const float4*)b;
    uint2* y = (uint2*)(Y + (size_t)row * Cc);
    #pragma unroll
    for (int i = 0; i < 8; i++) {
        float4 wv = w4[lane + i * 32];
        float4 bv = b4[lane + i * 32];
        __half2 o0 = __floats2half2_rn((v[i].x - mu) * rstd * wv.x + bv.x,
                                       (v[i].y - mu) * rstd * wv.y + bv.y);
        __half2 o1 = __floats2half2_rn((v[i].z - mu) * rstd * wv.z + bv.z,
                                       (v[i].w - mu) * rstd * wv.w + bv.w);
        uint2 pk;
        pk.x = *(uint32_t*)&o0;
        pk.y = *(uint32_t*)&o1;
        y[lane + i * 32] = pk;
    }
}

// ---------------- fp16 GEMM, 128x128 tile, K-chunk 64, 3-stage ring ----------------
// 8 warps = 2(m) x 4(n); warp tile 64x32.  Single barrier per iteration:
//   wait(1); barrier; prefetch(it+2); commit; compute(it)
// Prefetch target stage (it+2)%3 == (it-1)%3 was last read in iter it-1,
// strictly before barrier(it) -> race-free.
#define HG_STAGES 3
#define HG_AS (128*72)
#define HG_BS (64*136)
#define HG_SMEM (HG_STAGES*(HG_AS+HG_BS)*2)   // 107520 bytes

__global__ void __launch_bounds__(256, 2) hgemm_kernel(const __half* __restrict__ A,
                                                       const __half* __restrict__ B,
                                                       const float* __restrict__ bias,
                                                       const float* __restrict__ res,
                                                       float* __restrict__ outF,
                                                       __half* __restrict__ outH,
                                                       int M, int N, int K, int relu) {
    extern __shared__ __half hsm[];
    __half (*As)[128][72] = (__half(*)[128][72])hsm;
    __half (*Bs)[64][136] = (__half(*)[64][136])(hsm + HG_STAGES * HG_AS);
    int tid = threadIdx.x, lane = tid & 31, warp = tid >> 5;
    int wm = warp >> 2, wn = warp & 3;
    int m0 = blockIdx.y * 128, n0 = blockIdx.x * 128;

    float acc[4][4][4] = {};

    auto load_stage = [&](int k0, int st) {
        #pragma unroll
        for (int j = 0; j < 4; j++) {            // A: 128 rows x 64 cols = 1024 x 16B
            int idx = tid + j * 256;
            int row = idx >> 3, c = (idx & 7) * 8;
            cpa16(smem_u32(&As[st][row][c]), A + (size_t)(m0 + row) * K + k0 + c);
        }
        #pragma unroll
        for (int j = 0; j < 4; j++) {            // B: 64 rows x 128 cols = 1024 x 16B
            int idx = tid + j * 256;
            int row = idx >> 4, c = (idx & 15) * 8;
            cpa16(smem_u32(&Bs[st][row][c]), B + (size_t)(k0 + row) * N + n0 + c);
        }
    };

    int nIter = K >> 6;                 // 64-K chunks; K >= 128 always here
    load_stage(0, 0); CP_COMMIT();
    load_stage(64, 1); CP_COMMIT();

    for (int it = 0; it < nIter; it++) {
        CP_WAIT(1);                     // chunk `it` resident (per-thread)
        __syncthreads();                // visible to all threads
        if (it + 2 < nIter) load_stage((it + 2) << 6, (it + 2) % 3);
        CP_COMMIT();                    // uniform group count (may be empty)
        int st = it % 3;
        #pragma unroll
        for (int kk = 0; kk < 64; kk += 16) {
            uint32_t a[4][4];
            #pragma unroll
            for (int mi = 0; mi < 4; mi++)
                ldsm4(a[mi][0], a[mi][1], a[mi][2], a[mi][3],
                      smem_u32(&As[st][wm * 64 + mi * 16 + (lane & 15)][kk + (lane >> 4) * 8]));
            #pragma unroll
            for (int n2 = 0; n2 < 2; n2++) {
                uint32_t b0, b1, b2, b3;
                ldsm4t(b0, b1, b2, b3,
                       smem_u32(&Bs[st][kk + (lane & 15)][wn * 32 + n2 * 16 + (lane >> 4) * 8]));
                #pragma unroll
                for (int mi = 0; mi < 4; mi++) {
                    mma16816(acc[mi][n2 * 2],     a[mi][0], a[mi][1], a[mi][2], a[mi][3], b0, b1);
                    mma16816(acc[mi][n2 * 2 + 1], a[mi][0], a[mi][1], a[mi][2], a[mi][3], b2, b3);
                }
            }
        }
    }

    #pragma unroll
    for (int mi = 0; mi < 4; mi++) {
        #pragma unroll
        for (int ni = 0; ni < 4; ni++) {
            int col = n0 + wn * 32 + ni * 8 + (lane & 3) * 2;
            #pragma unroll
            for (int r = 0; r < 2; r++) {
                int row = m0 + wm * 64 + mi * 16 + (lane >> 2) + r * 8;
                float v0 = acc[mi][ni][r * 2], v1 = acc[mi][ni][r * 2 + 1];
                if (bias) { v0 += bias[col]; v1 += bias[col + 1]; }
                if (relu) { v0 = fmaxf(v0, 0.f); v1 = fmaxf(v1, 0.f); }
                size_t idx = (size_t)row * N + col;
                if (res) { v0 += res[idx]; v1 += res[idx + 1]; }
                if (outH) {
                    *(__half2*)&outH[idx] = __floats2half2_rn(v0, v1);
                } else {
                    *(float2*)&outF[idx] = make_float2(v0, v1);
                }
            }
        }
    }
}

// ---------------- fused flash attention, 4-stage cp.async K/V ring ----------------
#define FL_QS (128*72)
#define FL_KS (64*72)
#define FL_SMEM ((FL_QS + 8*FL_KS)*2)    // 92160 bytes

__global__ void __launch_bounds__(256, 2) flash_kernel(const __half* __restrict__ Q,
                                                       const __half* __restrict__ Kp,
                                                       const __half* __restrict__ Vp,
                                                       __half* __restrict__ Mg,
                                                       int strideQ, int pitchQ,
                                                       int strideKV, int pitchKV, int causal) {
    extern __shared__ __half fsm[];
    __half (*Qs)[72] = (__half(*)[72])fsm;
    __half (*Ks)[64][72] = (__half(*)[64][72])(fsm + FL_QS);
    __half (*Vs)[64][72] = (__half(*)[64][72])(fsm + FL_QS + 4 * FL_KS);
    int tid = threadIdx.x, lane = tid & 31, w = tid >> 5;
    int h = blockIdx.y;
    int t0 = (gridDim.x - 1 - blockIdx.x) * 128;
    const __half* Qb = Q  + h * pitchQ;
    const __half* Kb = Kp + h * pitchKV;
    const __half* Vb = Vp + h * pitchKV;

    auto load_kv = [&](int s0, int st) {
        #pragma unroll
        for (int j = 0; j < 2; j++) {
            int idx = tid + j * 256;
            int row = idx >> 3, col = (idx & 7) * 8;
            cpa16(smem_u32(&Ks[st][row][col]), Kb + (size_t)(s0 + row) * strideKV + col);
            cpa16(smem_u32(&Vs[st][row][col]), Vb + (size_t)(s0 + row) * strideKV + col);
        }
    };

    int sEnd = causal ? (t0 + 128) : Tt;
    int nT = sEnd >> 6;
    load_kv(0, 0); CP_COMMIT();
    if (nT > 1) load_kv(64, 1);
    CP_COMMIT();

    const __half2 sc = __float2half2_rn(0.125f);
    #pragma unroll
    for (int j = 0; j < 4; j++) {
        int idx = tid + j * 256;
        int row = idx >> 3, col = (idx & 7) * 8;
        uint4 v = *(const uint4*)(Qb + (size_t)(t0 + row) * strideQ + col);
        __half2* h2 = (__half2*)&v;
        #pragma unroll
        for (int q = 0; q < 4; q++) h2[q] = __hmul2(h2[q], sc);
        *(uint4*)&Qs[row][col] = v;
    }
    __syncthreads();

    uint32_t qf[4][4];
    #pragma unroll
    for (int kk = 0; kk < 4; kk++)
        ldsm4(qf[kk][0], qf[kk][1], qf[kk][2], qf[kk][3],
              smem_u32(&Qs[w * 16 + (lane & 15)][kk * 16 + (lane >> 4) * 8]));

    float m_[2] = {-1e30f, -1e30f}, l_[2] = {0.f, 0.f};
    float acc[8][4] = {};

    for (int i = 0; i < nT; i++) {
        if (i + 2 < nT) load_kv((i + 2) << 6, (i + 2) & 3);
        CP_COMMIT();
        CP_WAIT(2);
        __syncthreads();
        int st = i & 3;
        int s0 = i << 6;

        float sacc[8][4] = {};
        #pragma unroll
        for (int kk = 0; kk < 4; kk++) {
            #pragma unroll
            for (int sg = 0; sg < 4; sg++) {
                uint32_t b0, b1, b2, b3;
                ldsm4(b0, b1, b2, b3,
                      smem_u32(&Ks[st][sg * 16 + (lane & 7) + ((lane >> 4) << 3)][kk * 16 + ((lane >> 3) & 1) * 8]));
                mma16816(sacc[sg * 2],     qf[kk][0], qf[kk][1], qf[kk][2], qf[kk][3], b0, b1);
                mma16816(sacc[sg * 2 + 1], qf[kk][0], qf[kk][1], qf[kk][2], qf[kk][3], b2, b3);
            }
        }

        if (causal && s0 + 63 > t0 + w * 16) {
            int tr0 = t0 + w * 16 + (lane >> 2);
            int tr1 = tr0 + 8;
            #pragma unroll
            for (int ni = 0; ni < 8; ni++) {
                int s = s0 + ni * 8 + (lane & 3) * 2;
                if (s > tr0)     sacc[ni][0] = -1e30f;
                if (s + 1 > tr0) sacc[ni][1] = -1e30f;
                if (s > tr1)     sacc[ni][2] = -1e30f;
                if (s + 1 > tr1) sacc[ni][3] = -1e30f;
            }
        }

        __half2 ph[8][2];
        #pragma unroll
        for (int r = 0; r < 2; r++) {
            float rm = -1e30f;
            #pragma unroll
            for (int ni = 0; ni < 8; ni++)
                rm = fmaxf(rm, fmaxf(sacc[ni][r * 2], sacc[ni][r * 2 + 1]));
            rm = fmaxf(rm, __shfl_xor_sync(0xffffffffu, rm, 1));
            rm = fmaxf(rm, __shfl_xor_sync(0xffffffffu, rm, 2));
            float mn  = fmaxf(m_[r], rm);
            float fac = __expf(m_[r] - mn);
            float ls = 0.f;
            #pragma unroll
            for (int ni = 0; ni < 8; ni++) {
                float e0 = __expf(sacc[ni][r * 2]     - mn);
                float e1 = __expf(sacc[ni][r * 2 + 1] - mn);
                ls += e0 + e1;
                ph[ni][r] = __floats2half2_rn(e0, e1);
            }
            ls += __shfl_xor_sync(0xffffffffu, ls, 1);
            ls += __shfl_xor_sync(0xffffffffu, ls, 2);
            l_[r] = l_[r] * fac + ls;
            m_[r] = mn;
            #pragma unroll
            for (int ni = 0; ni < 8; ni++) { acc[ni][r * 2] *= fac; acc[ni][r * 2 + 1] *= fac; }
        }

        #pragma unroll
        for (int kk = 0; kk < 4; kk++) {
            uint32_t a0 = *(uint32_t*)&ph[2 * kk][0];
            uint32_t a1 = *(uint32_t*)&ph[2 * kk][1];
            uint32_t a2 = *(uint32_t*)&ph[2 * kk + 1][0];
            uint32_t a3 = *(uint32_t*)&ph[2 * kk + 1][1];
            #pragma unroll
            for (int n2 = 0; n2 < 4; n2++) {
                uint32_t b0, b1, b2, b3;
                ldsm4t(b0, b1, b2, b3,
                       smem_u32(&Vs[st][kk * 16 + (lane & 15)][n2 * 16 + (lane >> 4) * 8]));
                mma16816(acc[n2 * 2],     a0, a1, a2, a3, b0, b1);
                mma16816(acc[n2 * 2 + 1], a0, a1, a2, a3, b2, b3);
            }
        }
    }

    float inv0 = 1.f / l_[0], inv1 = 1.f / l_[1];
    #pragma unroll
    for (int ni = 0; ni < 8; ni++) {
        int d = ni * 8 + (lane & 3) * 2;
        int t = t0 + w * 16 + (lane >> 2);
        *(__half2*)&Mg[(size_t)t * Cc + h * Dd + d] =
            __floats2half2_rn(acc[ni][0] * inv0, acc[ni][1] * inv0);
        *(__half2*)&Mg[(size_t)(t + 8) * Cc + h * Dd + d] =
            __floats2half2_rn(acc[ni][2] * inv1, acc[ni][3] * inv1);
    }
}

// ======================================================================
extern "C" void kernel_launch(void* const* d_in, const int* in_sizes, int n_in,
                              void* d_out, int out_size) {
    const float* x       = (const float*)d_in[0];
    const float* enc     = (const float*)d_in[1];
    const float* w_qkv   = (const float*)d_in[2];
    const float* w_proj  = (const float*)d_in[3];
    const float* b_proj  = (const float*)d_in[4];
    const float* cw_q    = (const float*)d_in[5];
    const float* cw_kv   = (const float*)d_in[6];
    const float* cw_proj = (const float*)d_in[7];
    const float* cb_proj = (const float*)d_in[8];
    const float* ff1_w1  = (const float*)d_in[9];
    const float* ff1_b1  = (const float*)d_in[10];
    const float* ff1_w2  = (const float*)d_in[11];
    const float* ff1_b2  = (const float*)d_in[12];
    const float* ff2_w1  = (const float*)d_in[13];
    const float* ff2_b1  = (const float*)d_in[14];
    const float* ff2_w2  = (const float*)d_in[15];
    const float* ff2_b2  = (const float*)d_in[16];
    const float* ln1_w = (const float*)d_in[17]; const float* ln1_b = (const float*)d_in[18];
    const float* ln2_w = (const float*)d_in[19]; const float* ln2_b = (const float*)d_in[20];
    const float* ln3_w = (const float*)d_in[21]; const float* ln3_b = (const float*)d_in[22];
    const float* ln4_w = (const float*)d_in[23]; const float* ln4_b = (const float*)d_in[24];

    float *px;
    __half *pln, *penc, *pwqkv, *pcwq, *pcwkv, *pwproj, *pcwproj;
    __half *pf11, *pf12, *pf21, *pf22;
    __half *py, *pcq, *pkv, *pm, *pff;
    cudaGetSymbolAddress((void**)&px,     g_x);
    cudaGetSymbolAddress((void**)&pln,    h_ln);
    cudaGetSymbolAddress((void**)&penc,   h_enc);
    cudaGetSymbolAddress((void**)&pwqkv,  h_wqkv);
    cudaGetSymbolAddress((void**)&pcwq,   h_cwq);
    cudaGetSymbolAddress((void**)&pcwkv,  h_cwkv);
    cudaGetSymbolAddress((void**)&pwproj, h_wproj);
    cudaGetSymbolAddress((void**)&pcwproj,h_cwproj);
    cudaGetSymbolAddress((void**)&pf11,   h_ff1w1);
    cudaGetSymbolAddress((void**)&pf12,   h_ff1w2);
    cudaGetSymbolAddress((void**)&pf21,   h_ff2w1);
    cudaGetSymbolAddress((void**)&pf22,   h_ff2w2);
    cudaGetSymbolAddress((void**)&py,     h_y);
    cudaGetSymbolAddress((void**)&pcq,    h_cq);
    cudaGetSymbolAddress((void**)&pkv,    h_kv);
    cudaGetSymbolAddress((void**)&pm,     h_m);
    cudaGetSymbolAddress((void**)&pff,    h_ff);

    cudaFuncSetAttribute(hgemm_kernel, cudaFuncAttributeMaxDynamicSharedMemorySize, HG_SMEM);
    cudaFuncSetAttribute(flash_kernel, cudaFuncAttributeMaxDynamicSharedMemorySize, FL_SMEM);

    auto cgrid = [](int n) { return (n + 255) / 256; };

    // ---- critical-path converts on the capture stream ----
    pack_w_kernel<<<cgrid(Hh*Cc*192/8), 256>>>(w_qkv, pwqkv, 192);
    cudaMemcpyAsync(px, x, (size_t)MM * Cc * sizeof(float), cudaMemcpyDeviceToDevice, 0);
    cudaEventRecord(g_ev1, 0);

    // ---- converts + cross-KV GEMM on side stream ----
    cudaStreamWaitEvent(g_s2, g_ev1, 0);
    pack_w_kernel<<<cgrid(Hh*Cc*64/8),  256, 0, g_s2>>>(cw_q,  pcwq,  64);
    pack_w_kernel<<<cgrid(Hh*Cc*128/8), 256, 0, g_s2>>>(cw_kv, pcwkv, 128);
    f2h_kernel<<<cgrid(Cc*Cc/4),  256, 0, g_s2>>>(w_proj,  pwproj,  Cc*Cc/4);
    f2h_kernel<<<cgrid(Cc*Cc/4),  256, 0, g_s2>>>(cw_proj, pcwproj, Cc*Cc/4);
    f2h_kernel<<<cgrid(Cc*FFF/4), 256, 0, g_s2>>>(ff1_w1, pf11, Cc*FFF/4);
    f2h_kernel<<<cgrid(FFF*Cc/4), 256, 0, g_s2>>>(ff1_w2, pf12, FFF*Cc/4);
    f2h_kernel<<<cgrid(Cc*FFF/4), 256, 0, g_s2>>>(ff2_w1, pf21, Cc*FFF/4);
    f2h_kernel<<<cgrid(FFF*Cc/4), 256, 0, g_s2>>>(ff2_w2, pf22, FFF*Cc/4);
    f2h_kernel<<<cgrid(MM*Cc/4),  256, 0, g_s2>>>(enc, penc, MM*Cc/4);
    cudaEventRecord(g_ev2, g_s2);            // weights ready
    hgemm_kernel<<<dim3(16, 32), 256, HG_SMEM, g_s2>>>(penc, pcwkv, nullptr, nullptr, nullptr, pkv, MM, 2048, Cc, 0);
    cudaEventRecord(g_ev3, g_s2);            // cross K/V ready

    // ---- per-batch pipelines on 4 streams ----
    auto run_batch = [&](int b, cudaStream_t st) {
        size_t oc = (size_t)b * Tt * Cc;
        float*  pxb  = px  + oc;
        __half* plnb = pln + oc;
        __half* pyb  = py  + (size_t)b * Tt * 3072;
        __half* pcqb = pcq + oc;
        __half* pkvb = pkv + (size_t)b * Tt * 2048;
        __half* pmb  = pm  + oc;
        __half* pffb = pff + (size_t)b * Tt * FFF;
        float*  poutb = (float*)d_out + oc;

        // 1) causal self-attention
        ln_kernel<<<Tt/8, 256, 0, st>>>(pxb, ln1_w, ln1_b, plnb);
        hgemm_kernel<<<dim3(24, 8), 256, HG_SMEM, st>>>(plnb, pwqkv, nullptr, nullptr, nullptr, pyb, Tt, 3072, Cc, 0);
        flash_kernel<<<dim3(8, Hh), 256, FL_SMEM, st>>>(pyb, pyb + 64, pyb + 128, pmb, 3072, 192, 3072, 192, 1);
        cudaStreamWaitEvent(st, g_ev2, 0);
        hgemm_kernel<<<dim3(8, 8), 256, HG_SMEM, st>>>(pmb, pwproj, b_proj, pxb, pxb, nullptr, Tt, Cc, Cc, 0);

        // 2) feed-forward 1
        ln_kernel<<<Tt/8, 256, 0, st>>>(pxb, ln2_w, ln2_b, plnb);
        hgemm_kernel<<<dim3(32, 8), 256, HG_SMEM, st>>>(plnb, pf11, ff1_b1, nullptr, nullptr, pffb, Tt, FFF, Cc, 1);
        hgemm_kernel<<<dim3(8, 8), 256, HG_SMEM, st>>>(pffb, pf12, ff1_b2, pxb, pxb, nullptr, Tt, Cc, FFF, 0);

        // 3) cross-attention
        ln_kernel<<<Tt/8, 256, 0, st>>>(pxb, ln3_w, ln3_b, plnb);
        hgemm_kernel<<<dim3(8, 8), 256, HG_SMEM, st>>>(plnb, pcwq, nullptr, nullptr, nullptr, pcqb, Tt, 1024, Cc, 0);
        cudaStreamWaitEvent(st, g_ev3, 0);
        flash_kernel<<<dim3(8, Hh), 256, FL_SMEM, st>>>(pcqb, pkvb, pkvb + 64, pmb, 1024, 64, 2048, 128, 0);
        hgemm_kernel<<<dim3(8, 8), 256, HG_SMEM, st>>>(pmb, pcwproj, cb_proj, pxb, pxb, nullptr, Tt, Cc, Cc, 0);

        // 4) feed-forward 2 -> d_out
        ln_kernel<<<Tt/8, 256, 0, st>>>(pxb, ln4_w, ln4_b, plnb);
        hgemm_kernel<<<dim3(32, 8), 256, HG_SMEM, st>>>(plnb, pf21, ff2_b1, nullptr, nullptr, pffb, Tt, FFF, Cc, 1);
        hgemm_kernel<<<dim3(8, 8), 256, HG_SMEM, st>>>(pffb, pf22, ff2_b2, pxb, poutb, nullptr, Tt, Cc, FFF, 0);
    };

    for (int i = 0; i < 3; i++) cudaStreamWaitEvent(g_sb[i], g_ev1, 0);
    run_batch(0, 0);
    for (int i = 0; i < 3; i++) run_batch(i + 1, g_sb[i]);

    for (int i = 0; i < 3; i++) {
        cudaEventRecord(g_evb[i], g_sb[i]);
        cudaStreamWaitEvent(0, g_evb[i], 0);
    }
    cudaStreamWaitEvent(0, g_ev3, 0);
}

// round 15
// speedup vs baseline: 1.0937x; 1.0438x over previous
#include <cuda_runtime.h>
#include <cuda_fp16.h>
#include <cstdint>
#include <math.h>

#define Bz  4
#define Tt  1024
#define Cc  1024
#define Hh  16
#define Dd  64
#define FFF 4096
#define MM  (Bz*Tt)           // 4096
#define NHEADS (Bz*Hh)        // 64

// ---------------- scratch (device globals) ----------------
__device__ float  g_x   [MM*Cc];                 // fp32 residual stream (first write: proj1 epilogue)
__device__ __half h_ln  [MM*Cc];
__device__ __half h_enc [MM*Cc];
__device__ __half h_wqkv[Cc*Hh*3*Dd];
__device__ __half h_cwq [Cc*Hh*Dd];
__device__ __half h_cwkv[Cc*Hh*2*Dd];
__device__ __half h_wproj[Cc*Cc];
__device__ __half h_cwproj[Cc*Cc];
__device__ __half h_ff1w1[Cc*FFF];
__device__ __half h_ff1w2[FFF*Cc];
__device__ __half h_ff2w1[Cc*FFF];
__device__ __half h_ff2w2[FFF*Cc];
__device__ __half h_y   [MM*Hh*3*Dd];            // self-attn qkv packed
__device__ __half h_cq  [MM*Cc];                 // cross-attn Q
__device__ __half h_kv  [MM*Hh*2*Dd];            // cross-attn K|V packed
__device__ __half h_m   [MM*Cc];                 // merged attention out
__device__ __half h_ff  [MM*FFF];

// ---------------- streams/events (created once, pre-main) ----------------
static cudaStream_t g_s2, g_sb[3];
static cudaEvent_t  g_ev0, g_ev1, g_ev2, g_ev3, g_evb[3];
struct _StreamInit {
    _StreamInit() {
        cudaStreamCreateWithFlags(&g_s2, cudaStreamNonBlocking);
        for (int i = 0; i < 3; i++) cudaStreamCreateWithFlags(&g_sb[i], cudaStreamNonBlocking);
        cudaEventCreateWithFlags(&g_ev0, cudaEventDisableTiming);
        cudaEventCreateWithFlags(&g_ev1, cudaEventDisableTiming);
        cudaEventCreateWithFlags(&g_ev2, cudaEventDisableTiming);
        cudaEventCreateWithFlags(&g_ev3, cudaEventDisableTiming);
        for (int i = 0; i < 3; i++) cudaEventCreateWithFlags(&g_evb[i], cudaEventDisableTiming);
    }
};
static _StreamInit _stream_init_once;

// ---------------- mma/ldmatrix/cp.async helpers ----------------
__device__ __forceinline__ uint32_t smem_u32(const void* p) {
    return (uint32_t)__cvta_generic_to_shared(p);
}
__device__ __forceinline__ void ldsm4(uint32_t& r0, uint32_t& r1, uint32_t& r2, uint32_t& r3, uint32_t a) {
    asm volatile("ldmatrix.sync.aligned.m8n8.x4.shared.b16 {%0,%1,%2,%3}, [%4];"
                 : "=r"(r0), "=r"(r1), "=r"(r2), "=r"(r3) : "r"(a));
}
__device__ __forceinline__ void ldsm4t(uint32_t& r0, uint32_t& r1, uint32_t& r2, uint32_t& r3, uint32_t a) {
    asm volatile("ldmatrix.sync.aligned.m8n8.x4.trans.shared.b16 {%0,%1,%2,%3}, [%4];"
                 : "=r"(r0), "=r"(r1), "=r"(r2), "=r"(r3) : "r"(a));
}
__device__ __forceinline__ void mma16816(float* c, uint32_t a0, uint32_t a1, uint32_t a2, uint32_t a3,
                                         uint32_t b0, uint32_t b1) {
    asm volatile("mma.sync.aligned.m16n8k16.row.col.f32.f16.f16.f32 "
                 "{%0,%1,%2,%3},{%4,%5,%6,%7},{%8,%9},{%0,%1,%2,%3};"
                 : "+f"(c[0]), "+f"(c[1]), "+f"(c[2]), "+f"(c[3])
                 : "r"(a0), "r"(a1), "r"(a2), "r"(a3), "r"(b0), "r"(b1));
}
__device__ __forceinline__ void cpa16(uint32_t dst, const void* src) {
    asm volatile("cp.async.cg.shared.global [%0], [%1], 16;" :: "r"(dst), "l"(src));
}
#define CP_COMMIT()  asm volatile("cp.async.commit_group;")
#define CP_WAIT(n)   asm volatile("cp.async.wait_group %0;" :: "n"(n) : "memory")

// ---------------- converts ----------------
__global__ void f2h_kernel(const float* __restrict__ src, __half* __restrict__ dst, int n4) {
    int i = blockIdx.x * blockDim.x + threadIdx.x;
    if (i >= n4) return;
    float4 v = ((const float4*)src)[i];
    __half2* o = (__half2*)dst + i * 2;
    o[0] = __floats2half2_rn(v.x, v.y);
    o[1] = __floats2half2_rn(v.z, v.w);
}
__global__ void pack_w_kernel(const float* __restrict__ W, __half* __restrict__ Wt, int J) {
    int i = blockIdx.x * blockDim.x + threadIdx.x;
    int J8 = J >> 3;
    int total8 = Hh * Cc * J8;
    if (i >= total8) return;
    int j8 = i % J8;
    int c = (i / J8) % Cc;
    int h = i / (J8 * Cc);
    const float4* src = (const float4*)(W + (size_t)(h * Cc + c) * J + j8 * 8);
    float4 v0 = src[0], v1 = src[1];
    __half2 o[4];
    o[0] = __floats2half2_rn(v0.x, v0.y); o[1] = __floats2half2_rn(v0.z, v0.w);
    o[2] = __floats2half2_rn(v1.x, v1.y); o[3] = __floats2half2_rn(v1.z, v1.w);
    *(uint4*)(Wt + (size_t)c * (Hh * J) + h * J + j8 * 8) = *(uint4*)o;
}

// ---------------- layernorm: warp-per-row ----------------
__global__ void __launch_bounds__(256) ln_kernel(const float* __restrict__ X,
                                                 const float* __restrict__ w,
                                                 const float* __restrict__ b,
                                                 __half* __restrict__ Y) {
    int warp = threadIdx.x >> 5, lane = threadIdx.x & 31;
    int row = blockIdx.x * 8 + warp;
    const float4* x4 = (const float4*)(X + (size_t)row * Cc);
    float4 v[8];
    float s = 0.f, sq = 0.f;
    #pragma unroll
    for (int i = 0; i < 8; i++) {
        v[i] = x4[lane + i * 32];
        s  += v[i].x + v[i].y + v[i].z + v[i].w;
        sq += v[i].x*v[i].x + v[i].y*v[i].y + v[i].z*v[i].z + v[i].w*v[i].w;
    }
    #pragma unroll
    for (int o = 16; o > 0; o >>= 1) {
        s  += __shfl_xor_sync(0xffffffffu, s,  o);
        sq += __shfl_xor_sync(0xffffffffu, sq, o);
    }
    float mu   = s / Cc;
    float rstd = rsqrtf(sq / Cc - mu * mu + 1e-5f);
    const float4* w4 = (const float4*)w;
    const float4* b4 = (const float4*)b;
    uint2* y = (uint2*)(Y + (size_t)row * Cc);
    #pragma unroll
    for (int i = 0; i < 8; i++) {
        float4 wv = w4[lane + i * 32];
        float4 bv = b4[lane + i * 32];
        __half2 o0 = __floats2half2_rn((v[i].x - mu) * rstd * wv.x + bv.x,
                                       (v[i].y - mu) * rstd * wv.y + bv.y);
        __half2 o1 = __floats2half2_rn((v[i].z - mu) * rstd * wv.z + bv.z,
                                       (v[i].w - mu) * rstd * wv.w + bv.w);
        uint2 pk;
        pk.x = *(uint32_t*)&o0;
        pk.y = *(uint32_t*)&o1;
        y[lane + i * 32] = pk;
    }
}

// ---------------- fp16 tensor-core GEMM, 4-stage cp.async ring (R9 config) ----
#define HG_STAGES 4
#define HG_AS (128*40)
#define HG_BS (32*136)
#define HG_SMEM (HG_STAGES*(HG_AS+HG_BS)*2)   // 75776 bytes

__global__ void __launch_bounds__(256, 2) hgemm_kernel(const __half* __restrict__ A,
                                                       const __half* __restrict__ B,
                                                       const float* __restrict__ bias,
                                                       const float* __restrict__ res,
                                                       float* __restrict__ outF,
                                                       __half* __restrict__ outH,
                                                       int M, int N, int K, int relu) {
    extern __shared__ __half hsm[];
    __half (*As)[128][40] = (__half(*)[128][40])hsm;
    __half (*Bs)[32][136] = (__half(*)[32][136])(hsm + HG_STAGES * HG_AS);
    int tid = threadIdx.x, lane = tid & 31, warp = tid >> 5;
    int wm = warp >> 2, wn = warp & 3;
    int m0 = blockIdx.y * 128, n0 = blockIdx.x * 128;

    float acc[4][4][4] = {};

    auto load_stage = [&](int k0, int st) {
        #pragma unroll
        for (int j = 0; j < 2; j++) {
            int idx = tid + j * 256;
            int row = idx >> 2, c = (idx & 3) * 8;
            cpa16(smem_u32(&As[st][row][c]), A + (size_t)(m0 + row) * K + k0 + c);
        }
        #pragma unroll
        for (int j = 0; j < 2; j++) {
            int idx = tid + j * 256;
            int row = idx >> 4, c = (idx & 15) * 8;
            cpa16(smem_u32(&Bs[st][row][c]), B + (size_t)(k0 + row) * N + n0 + c);
        }
    };

    int nIter = K >> 5;
    load_stage(0, 0); CP_COMMIT();
    load_stage(32, 1); CP_COMMIT();

    for (int it = 0; it < nIter; it++) {
        if (it + 2 < nIter) load_stage((it + 2) << 5, (it + 2) & 3);
        CP_COMMIT();
        CP_WAIT(2);
        __syncthreads();
        int st = it & 3;
        #pragma unroll
        for (int kk = 0; kk < 32; kk += 16) {
            uint32_t a[4][4];
            #pragma unroll
            for (int mi = 0; mi < 4; mi++)
                ldsm4(a[mi][0], a[mi][1], a[mi][2], a[mi][3],
                      smem_u32(&As[st][wm * 64 + mi * 16 + (lane & 15)][kk + (lane >> 4) * 8]));
            #pragma unroll
            for (int n2 = 0; n2 < 2; n2++) {
                uint32_t b0, b1, b2, b3;
                ldsm4t(b0, b1, b2, b3,
                       smem_u32(&Bs[st][kk + (lane & 15)][wn * 32 + n2 * 16 + (lane >> 4) * 8]));
                #pragma unroll
                for (int mi = 0; mi < 4; mi++) {
                    mma16816(acc[mi][n2 * 2],     a[mi][0], a[mi][1], a[mi][2], a[mi][3], b0, b1);
                    mma16816(acc[mi][n2 * 2 + 1], a[mi][0], a[mi][1], a[mi][2], a[mi][3], b2, b3);
                }
            }
        }
    }

    #pragma unroll
    for (int mi = 0; mi < 4; mi++) {
        #pragma unroll
        for (int ni = 0; ni < 4; ni++) {
            int col = n0 + wn * 32 + ni * 8 + (lane & 3) * 2;
            #pragma unroll
            for (int r = 0; r < 2; r++) {
                int row = m0 + wm * 64 + mi * 16 + (lane >> 2) + r * 8;
                float v0 = acc[mi][ni][r * 2], v1 = acc[mi][ni][r * 2 + 1];
                if (bias) { v0 += bias[col]; v1 += bias[col + 1]; }
                if (relu) { v0 = fmaxf(v0, 0.f); v1 = fmaxf(v1, 0.f); }
                size_t idx = (size_t)row * N + col;
                if (res) { v0 += res[idx]; v1 += res[idx + 1]; }
                if (outH) {
                    *(__half2*)&outH[idx] = __floats2half2_rn(v0, v1);
                } else {
                    *(float2*)&outF[idx] = make_float2(v0, v1);
                }
            }
        }
    }
}

// ---------------- fused flash attention, 4-stage cp.async K/V ring (R9) ----------------
#define FL_QS (128*72)
#define FL_KS (64*72)
#define FL_SMEM ((FL_QS + 8*FL_KS)*2)    // 92160 bytes

__global__ void __launch_bounds__(256, 2) flash_kernel(const __half* __restrict__ Q,
                                                       const __half* __restrict__ Kp,
                                                       const __half* __restrict__ Vp,
                                                       __half* __restrict__ Mg,
                                                       int strideQ, int pitchQ,
                                                       int strideKV, int pitchKV, int causal) {
    extern __shared__ __half fsm[];
    __half (*Qs)[72] = (__half(*)[72])fsm;
    __half (*Ks)[64][72] = (__half(*)[64][72])(fsm + FL_QS);
    __half (*Vs)[64][72] = (__half(*)[64][72])(fsm + FL_QS + 4 * FL_KS);
    int tid = threadIdx.x, lane = tid & 31, w = tid >> 5;
    int h = blockIdx.y;
    int t0 = (gridDim.x - 1 - blockIdx.x) * 128;    // heavy tiles first
    const __half* Qb = Q  + h * pitchQ;
    const __half* Kb = Kp + h * pitchKV;
    const __half* Vb = Vp + h * pitchKV;

    auto load_kv = [&](int s0, int st) {
        #pragma unroll
        for (int j = 0; j < 2; j++) {
            int idx = tid + j * 256;
            int row = idx >> 3, col = (idx & 7) * 8;
            cpa16(smem_u32(&Ks[st][row][col]), Kb + (size_t)(s0 + row) * strideKV + col);
            cpa16(smem_u32(&Vs[st][row][col]), Vb + (size_t)(s0 + row) * strideKV + col);
        }
    };

    int sEnd = causal ? (t0 + 128) : Tt;
    int nT = sEnd >> 6;
    load_kv(0, 0); CP_COMMIT();
    if (nT > 1) load_kv(64, 1);
    CP_COMMIT();

    const __half2 sc = __float2half2_rn(0.125f);
    #pragma unroll
    for (int j = 0; j < 4; j++) {
        int idx = tid + j * 256;
        int row = idx >> 3, col = (idx & 7) * 8;
        uint4 v = *(const uint4*)(Qb + (size_t)(t0 + row) * strideQ + col);
        __half2* h2 = (__half2*)&v;
        #pragma unroll
        for (int q = 0; q < 4; q++) h2[q] = __hmul2(h2[q], sc);
        *(uint4*)&Qs[row][col] = v;
    }
    __syncthreads();

    uint32_t qf[4][4];
    #pragma unroll
    for (int kk = 0; kk < 4; kk++)
        ldsm4(qf[kk][0], qf[kk][1], qf[kk][2], qf[kk][3],
              smem_u32(&Qs[w * 16 + (lane & 15)][kk * 16 + (lane >> 4) * 8]));

    float m_[2] = {-1e30f, -1e30f}, l_[2] = {0.f, 0.f};
    float acc[8][4] = {};

    for (int i = 0; i < nT; i++) {
        if (i + 2 < nT) load_kv((i + 2) << 6, (i + 2) & 3);
        CP_COMMIT();
        CP_WAIT(2);
        __syncthreads();
        int st = i & 3;
        int s0 = i << 6;

        float sacc[8][4] = {};
        #pragma unroll
        for (int kk = 0; kk < 4; kk++) {
            #pragma unroll
            for (int sg = 0; sg < 4; sg++) {
                uint32_t b0, b1, b2, b3;
                ldsm4(b0, b1, b2, b3,
                      smem_u32(&Ks[st][sg * 16 + (lane & 7) + ((lane >> 4) << 3)][kk * 16 + ((lane >> 3) & 1) * 8]));
                mma16816(sacc[sg * 2],     qf[kk][0], qf[kk][1], qf[kk][2], qf[kk][3], b0, b1);
                mma16816(sacc[sg * 2 + 1], qf[kk][0], qf[kk][1], qf[kk][2], qf[kk][3], b2, b3);
            }
        }

        if (causal && s0 + 63 > t0 + w * 16) {
            int tr0 = t0 + w * 16 + (lane >> 2);
            int tr1 = tr0 + 8;
            #pragma unroll
            for (int ni = 0; ni < 8; ni++) {
                int s = s0 + ni * 8 + (lane & 3) * 2;
                if (s > tr0)     sacc[ni][0] = -1e30f;
                if (s + 1 > tr0) sacc[ni][1] = -1e30f;
                if (s > tr1)     sacc[ni][2] = -1e30f;
                if (s + 1 > tr1) sacc[ni][3] = -1e30f;
            }
        }

        __half2 ph[8][2];
        #pragma unroll
        for (int r = 0; r < 2; r++) {
            float rm = -1e30f;
            #pragma unroll
            for (int ni = 0; ni < 8; ni++)
                rm = fmaxf(rm, fmaxf(sacc[ni][r * 2], sacc[ni][r * 2 + 1]));
            rm = fmaxf(rm, __shfl_xor_sync(0xffffffffu, rm, 1));
            rm = fmaxf(rm, __shfl_xor_sync(0xffffffffu, rm, 2));
            float mn  = fmaxf(m_[r], rm);
            float fac = __expf(m_[r] - mn);
            float ls = 0.f;
            #pragma unroll
            for (int ni = 0; ni < 8; ni++) {
                float e0 = __expf(sacc[ni][r * 2]     - mn);
                float e1 = __expf(sacc[ni][r * 2 + 1] - mn);
                ls += e0 + e1;
                ph[ni][r] = __floats2half2_rn(e0, e1);
            }
            ls += __shfl_xor_sync(0xffffffffu, ls, 1);
            ls += __shfl_xor_sync(0xffffffffu, ls, 2);
            l_[r] = l_[r] * fac + ls;
            m_[r] = mn;
            #pragma unroll
            for (int ni = 0; ni < 8; ni++) { acc[ni][r * 2] *= fac; acc[ni][r * 2 + 1] *= fac; }
        }

        #pragma unroll
        for (int kk = 0; kk < 4; kk++) {
            uint32_t a0 = *(uint32_t*)&ph[2 * kk][0];
            uint32_t a1 = *(uint32_t*)&ph[2 * kk][1];
            uint32_t a2 = *(uint32_t*)&ph[2 * kk + 1][0];
            uint32_t a3 = *(uint32_t*)&ph[2 * kk + 1][1];
            #pragma unroll
            for (int n2 = 0; n2 < 4; n2++) {
                uint32_t b0, b1, b2, b3;
                ldsm4t(b0, b1, b2, b3,
                       smem_u32(&Vs[st][kk * 16 + (lane & 15)][n2 * 16 + (lane >> 4) * 8]));
                mma16816(acc[n2 * 2],     a0, a1, a2, a3, b0, b1);
                mma16816(acc[n2 * 2 + 1], a0, a1, a2, a3, b2, b3);
            }
        }
    }

    float inv0 = 1.f / l_[0], inv1 = 1.f / l_[1];
    #pragma unroll
    for (int ni = 0; ni < 8; ni++) {
        int d = ni * 8 + (lane & 3) * 2;
        int t = t0 + w * 16 + (lane >> 2);
        *(__half2*)&Mg[(size_t)t * Cc + h * Dd + d] =
            __floats2half2_rn(acc[ni][0] * inv0, acc[ni][1] * inv0);
        *(__half2*)&Mg[(size_t)(t + 8) * Cc + h * Dd + d] =
            __floats2half2_rn(acc[ni][2] * inv1, acc[ni][3] * inv1);
    }
}

// ======================================================================
extern "C" void kernel_launch(void* const* d_in, const int* in_sizes, int n_in,
                              void* d_out, int out_size) {
    const float* x       = (const float*)d_in[0];
    const float* enc     = (const float*)d_in[1];
    const float* w_qkv   = (const float*)d_in[2];
    const float* w_proj  = (const float*)d_in[3];
    const float* b_proj  = (const float*)d_in[4];
    const float* cw_q    = (const float*)d_in[5];
    const float* cw_kv   = (const float*)d_in[6];
    const float* cw_proj = (const float*)d_in[7];
    const float* cb_proj = (const float*)d_in[8];
    const float* ff1_w1  = (const float*)d_in[9];
    const float* ff1_b1  = (const float*)d_in[10];
    const float* ff1_w2  = (const float*)d_in[11];
    const float* ff1_b2  = (const float*)d_in[12];
    const float* ff2_w1  = (const float*)d_in[13];
    const float* ff2_b1  = (const float*)d_in[14];
    const float* ff2_w2  = (const float*)d_in[15];
    const float* ff2_b2  = (const float*)d_in[16];
    const float* ln1_w = (const float*)d_in[17]; const float* ln1_b = (const float*)d_in[18];
    const float* ln2_w = (const float*)d_in[19]; const float* ln2_b = (const float*)d_in[20];
    const float* ln3_w = (const float*)d_in[21]; const float* ln3_b = (const float*)d_in[22];
    const float* ln4_w = (const float*)d_in[23]; const float* ln4_b = (const float*)d_in[24];

    float *px;
    __half *pln, *penc, *pwqkv, *pcwq, *pcwkv, *pwproj, *pcwproj;
    __half *pf11, *pf12, *pf21, *pf22;
    __half *py, *pcq, *pkv, *pm, *pff;
    cudaGetSymbolAddress((void**)&px,     g_x);
    cudaGetSymbolAddress((void**)&pln,    h_ln);
    cudaGetSymbolAddress((void**)&penc,   h_enc);
    cudaGetSymbolAddress((void**)&pwqkv,  h_wqkv);
    cudaGetSymbolAddress((void**)&pcwq,   h_cwq);
    cudaGetSymbolAddress((void**)&pcwkv,  h_cwkv);
    cudaGetSymbolAddress((void**)&pwproj, h_wproj);
    cudaGetSymbolAddress((void**)&pcwproj,h_cwproj);
    cudaGetSymbolAddress((void**)&pf11,   h_ff1w1);
    cudaGetSymbolAddress((void**)&pf12,   h_ff1w2);
    cudaGetSymbolAddress((void**)&pf21,   h_ff2w1);
    cudaGetSymbolAddress((void**)&pf22,   h_ff2w2);
    cudaGetSymbolAddress((void**)&py,     h_y);
    cudaGetSymbolAddress((void**)&pcq,    h_cq);
    cudaGetSymbolAddress((void**)&pkv,    h_kv);
    cudaGetSymbolAddress((void**)&pm,     h_m);
    cudaGetSymbolAddress((void**)&pff,    h_ff);

    cudaFuncSetAttribute(hgemm_kernel, cudaFuncAttributeMaxDynamicSharedMemorySize, HG_SMEM);
    cudaFuncSetAttribute(flash_kernel, cudaFuncAttributeMaxDynamicSharedMemorySize, FL_SMEM);

    auto cgrid = [](int n) { return (n + 255) / 256; };

    // ---- fork root: capture-origin event BEFORE any work ----
    cudaEventRecord(g_ev0, 0);

    // ---- critical-path convert on the capture stream ----
    pack_w_kernel<<<cgrid(Hh*Cc*192/8), 256>>>(w_qkv, pwqkv, 192);
    cudaEventRecord(g_ev1, 0);               // qkv weights ready

    // ---- converts + cross-KV GEMM on side stream (joins capture via ev0) ----
    cudaStreamWaitEvent(g_s2, g_ev0, 0);
    pack_w_kernel<<<cgrid(Hh*Cc*64/8),  256, 0, g_s2>>>(cw_q,  pcwq,  64);
    pack_w_kernel<<<cgrid(Hh*Cc*128/8), 256, 0, g_s2>>>(cw_kv, pcwkv, 128);
    f2h_kernel<<<cgrid(Cc*Cc/4),  256, 0, g_s2>>>(w_proj,  pwproj,  Cc*Cc/4);
    f2h_kernel<<<cgrid(Cc*Cc/4),  256, 0, g_s2>>>(cw_proj, pcwproj, Cc*Cc/4);
    f2h_kernel<<<cgrid(Cc*FFF/4), 256, 0, g_s2>>>(ff1_w1, pf11, Cc*FFF/4);
    f2h_kernel<<<cgrid(FFF*Cc/4), 256, 0, g_s2>>>(ff1_w2, pf12, FFF*Cc/4);
    f2h_kernel<<<cgrid(Cc*FFF/4), 256, 0, g_s2>>>(ff2_w1, pf21, Cc*FFF/4);
    f2h_kernel<<<cgrid(FFF*Cc/4), 256, 0, g_s2>>>(ff2_w2, pf22, FFF*Cc/4);
    f2h_kernel<<<cgrid(MM*Cc/4),  256, 0, g_s2>>>(enc, penc, MM*Cc/4);
    cudaEventRecord(g_ev2, g_s2);            // weights ready
    hgemm_kernel<<<dim3(16, 32), 256, HG_SMEM, g_s2>>>(penc, pcwkv, nullptr, nullptr, nullptr, pkv, MM, 2048, Cc, 0);
    cudaEventRecord(g_ev3, g_s2);            // cross K/V ready

    // ---- per-batch pipelines on 4 streams ----
    auto run_batch = [&](int b, cudaStream_t st) {
        size_t oc = (size_t)b * Tt * Cc;
        const float* pxin = x + oc;          // input slice (residual seed)
        float*  pxb  = px  + oc;             // residual stream (first write: proj1)
        __half* plnb = pln + oc;
        __half* pyb  = py  + (size_t)b * Tt * 3072;
        __half* pcqb = pcq + oc;
        __half* pkvb = pkv + (size_t)b * Tt * 2048;
        __half* pmb  = pm  + oc;
        __half* pffb = pff + (size_t)b * Tt * FFF;
        float*  poutb = (float*)d_out + oc;

        // 1) causal self-attention — ln1 reads the INPUT directly (no copy)
        ln_kernel<<<Tt/8, 256, 0, st>>>(pxin, ln1_w, ln1_b, plnb);
        if (st != 0) cudaStreamWaitEvent(st, g_ev1, 0);    // qkv weights ready
        hgemm_kernel<<<dim3(24, 8), 256, HG_SMEM, st>>>(plnb, pwqkv, nullptr, nullptr, nullptr, pyb, Tt, 3072, Cc, 0);
        flash_kernel<<<dim3(8, Hh), 256, FL_SMEM, st>>>(pyb, pyb + 64, pyb + 128, pmb, 3072, 192, 3072, 192, 1);
        cudaStreamWaitEvent(st, g_ev2, 0);
        // residual seed = input x; writes the fp32 residual stream px
        hgemm_kernel<<<dim3(8, 8), 256, HG_SMEM, st>>>(pmb, pwproj, b_proj, pxin, pxb, nullptr, Tt, Cc, Cc, 0);

        // 2) feed-forward 1
        ln_kernel<<<Tt/8, 256, 0, st>>>(pxb, ln2_w, ln2_b, plnb);
        hgemm_kernel<<<dim3(32, 8), 256, HG_SMEM, st>>>(plnb, pf11, ff1_b1, nullptr, nullptr, pffb, Tt, FFF, Cc, 1);
        hgemm_kernel<<<dim3(8, 8), 256, HG_SMEM, st>>>(pffb, pf12, ff1_b2, pxb, pxb, nullptr, Tt, Cc, FFF, 0);

        // 3) cross-attention
        ln_kernel<<<Tt/8, 256, 0, st>>>(pxb, ln3_w, ln3_b, plnb);
        hgemm_kernel<<<dim3(8, 8), 256, HG_SMEM, st>>>(plnb, pcwq, nullptr, nullptr, nullptr, pcqb, Tt, 1024, Cc, 0);
        cudaStreamWaitEvent(st, g_ev3, 0);
        flash_kernel<<<dim3(8, Hh), 256, FL_SMEM, st>>>(pcqb, pkvb, pkvb + 64, pmb, 1024, 64, 2048, 128, 0);
        hgemm_kernel<<<dim3(8, 8), 256, HG_SMEM, st>>>(pmb, pcwproj, cb_proj, pxb, pxb, nullptr, Tt, Cc, Cc, 0);

        // 4) feed-forward 2 -> d_out
        ln_kernel<<<Tt/8, 256, 0, st>>>(pxb, ln4_w, ln4_b, plnb);
        hgemm_kernel<<<dim3(32, 8), 256, HG_SMEM, st>>>(plnb, pf21, ff2_b1, nullptr, nullptr, pffb, Tt, FFF, Cc, 1);
        hgemm_kernel<<<dim3(8, 8), 256, HG_SMEM, st>>>(pffb, pf22, ff2_b2, pxb, poutb, nullptr, Tt, Cc, FFF, 0);
    };

    // batch streams join the capture via ev0 BEFORE any launch on them
    for (int i = 0; i < 3; i++) cudaStreamWaitEvent(g_sb[i], g_ev0, 0);
    run_batch(0, 0);
    for (int i = 0; i < 3; i++) run_batch(i + 1, g_sb[i]);

    // ---- join everything back into the capture stream ----
    for (int i = 0; i < 3; i++) {
        cudaEventRecord(g_evb[i], g_sb[i]);
        cudaStreamWaitEvent(0, g_evb[i], 0);
    }
    cudaStreamWaitEvent(0, g_ev3, 0);
}

// round 16
// speedup vs baseline: 1.1001x; 1.0059x over previous
#include <cuda_runtime.h>
#include <cuda_fp16.h>
#include <cstdint>
#include <math.h>

#define Bz  4
#define Tt  1024
#define Cc  1024
#define Hh  16
#define Dd  64
#define FFF 4096
#define MM  (Bz*Tt)           // 4096
#define NHEADS (Bz*Hh)        // 64

// ---------------- scratch (device globals) ----------------
__device__ __half h_x   [MM*Cc];                 // fp16 residual stream (first write: proj1 epilogue)
__device__ __half h_ln  [MM*Cc];
__device__ __half h_enc [MM*Cc];
__device__ __half h_wqkv[Cc*Hh*3*Dd];
__device__ __half h_cwq [Cc*Hh*Dd];
__device__ __half h_cwkv[Cc*Hh*2*Dd];
__device__ __half h_wproj[Cc*Cc];
__device__ __half h_cwproj[Cc*Cc];
__device__ __half h_ff1w1[Cc*FFF];
__device__ __half h_ff1w2[FFF*Cc];
__device__ __half h_ff2w1[Cc*FFF];
__device__ __half h_ff2w2[FFF*Cc];
__device__ __half h_y   [MM*Hh*3*Dd];            // self-attn qkv packed
__device__ __half h_cq  [MM*Cc];                 // cross-attn Q
__device__ __half h_kv  [MM*Hh*2*Dd];            // cross-attn K|V packed
__device__ __half h_m   [MM*Cc];                 // merged attention out
__device__ __half h_ff  [MM*FFF];

// ---------------- streams/events (created once, pre-main) ----------------
static cudaStream_t g_s2, g_sb[3];
static cudaEvent_t  g_ev0, g_ev1, g_ev2, g_ev3, g_evb[3];
struct _StreamInit {
    _StreamInit() {
        cudaStreamCreateWithFlags(&g_s2, cudaStreamNonBlocking);
        for (int i = 0; i < 3; i++) cudaStreamCreateWithFlags(&g_sb[i], cudaStreamNonBlocking);
        cudaEventCreateWithFlags(&g_ev0, cudaEventDisableTiming);
        cudaEventCreateWithFlags(&g_ev1, cudaEventDisableTiming);
        cudaEventCreateWithFlags(&g_ev2, cudaEventDisableTiming);
        cudaEventCreateWithFlags(&g_ev3, cudaEventDisableTiming);
        for (int i = 0; i < 3; i++) cudaEventCreateWithFlags(&g_evb[i], cudaEventDisableTiming);
    }
};
static _StreamInit _stream_init_once;

// ---------------- mma/ldmatrix/cp.async helpers ----------------
__device__ __forceinline__ uint32_t smem_u32(const void* p) {
    return (uint32_t)__cvta_generic_to_shared(p);
}
__device__ __forceinline__ void ldsm4(uint32_t& r0, uint32_t& r1, uint32_t& r2, uint32_t& r3, uint32_t a) {
    asm volatile("ldmatrix.sync.aligned.m8n8.x4.shared.b16 {%0,%1,%2,%3}, [%4];"
                 : "=r"(r0), "=r"(r1), "=r"(r2), "=r"(r3) : "r"(a));
}
__device__ __forceinline__ void ldsm4t(uint32_t& r0, uint32_t& r1, uint32_t& r2, uint32_t& r3, uint32_t a) {
    asm volatile("ldmatrix.sync.aligned.m8n8.x4.trans.shared.b16 {%0,%1,%2,%3}, [%4];"
                 : "=r"(r0), "=r"(r1), "=r"(r2), "=r"(r3) : "r"(a));
}
__device__ __forceinline__ void mma16816(float* c, uint32_t a0, uint32_t a1, uint32_t a2, uint32_t a3,
                                         uint32_t b0, uint32_t b1) {
    asm volatile("mma.sync.aligned.m16n8k16.row.col.f32.f16.f16.f32 "
                 "{%0,%1,%2,%3},{%4,%5,%6,%7},{%8,%9},{%0,%1,%2,%3};"
                 : "+f"(c[0]), "+f"(c[1]), "+f"(c[2]), "+f"(c[3])
                 : "r"(a0), "r"(a1), "r"(a2), "r"(a3), "r"(b0), "r"(b1));
}
__device__ __forceinline__ void cpa16(uint32_t dst, const void* src) {
    asm volatile("cp.async.cg.shared.global [%0], [%1], 16;" :: "r"(dst), "l"(src));
}
#define CP_COMMIT()  asm volatile("cp.async.commit_group;")
#define CP_WAIT(n)   asm volatile("cp.async.wait_group %0;" :: "n"(n) : "memory")

// ---------------- converts ----------------
__global__ void f2h_kernel(const float* __restrict__ src, __half* __restrict__ dst, int n4) {
    int i = blockIdx.x * blockDim.x + threadIdx.x;
    if (i >= n4) return;
    float4 v = ((const float4*)src)[i];
    __half2* o = (__half2*)dst + i * 2;
    o[0] = __floats2half2_rn(v.x, v.y);
    o[1] = __floats2half2_rn(v.z, v.w);
}
__global__ void pack_w_kernel(const float* __restrict__ W, __half* __restrict__ Wt, int J) {
    int i = blockIdx.x * blockDim.x + threadIdx.x;
    int J8 = J >> 3;
    int total8 = Hh * Cc * J8;
    if (i >= total8) return;
    int j8 = i % J8;
    int c = (i / J8) % Cc;
    int h = i / (J8 * Cc);
    const float4* src = (const float4*)(W + (size_t)(h * Cc + c) * J + j8 * 8);
    float4 v0 = src[0], v1 = src[1];
    __half2 o[4];
    o[0] = __floats2half2_rn(v0.x, v0.y); o[1] = __floats2half2_rn(v0.z, v0.w);
    o[2] = __floats2half2_rn(v1.x, v1.y); o[3] = __floats2half2_rn(v1.z, v1.w);
    *(uint4*)(Wt + (size_t)c * (Hh * J) + h * J + j8 * 8) = *(uint4*)o;
}

// ---------------- layernorm (fp32 input): warp-per-row ----------------
__global__ void __launch_bounds__(256) ln_kernel(const float* __restrict__ X,
                                                 const float* __restrict__ w,
                                                 const float* __restrict__ b,
                                                 __half* __restrict__ Y) {
    int warp = threadIdx.x >> 5, lane = threadIdx.x & 31;
    int row = blockIdx.x * 8 + warp;
    const float4* x4 = (const float4*)(X + (size_t)row * Cc);
    float4 v[8];
    float s = 0.f, sq = 0.f;
    #pragma unroll
    for (int i = 0; i < 8; i++) {
        v[i] = x4[lane + i * 32];
        s  += v[i].x + v[i].y + v[i].z + v[i].w;
        sq += v[i].x*v[i].x + v[i].y*v[i].y + v[i].z*v[i].z + v[i].w*v[i].w;
    }
    #pragma unroll
    for (int o = 16; o > 0; o >>= 1) {
        s  += __shfl_xor_sync(0xffffffffu, s,  o);
        sq += __shfl_xor_sync(0xffffffffu, sq, o);
    }
    float mu   = s / Cc;
    float rstd = rsqrtf(sq / Cc - mu * mu + 1e-5f);
    const float4* w4 = (const float4*)w;
    const float4* b4 = (const float4*)b;
    uint2* y = (uint2*)(Y + (size_t)row * Cc);
    #pragma unroll
    for (int i = 0; i < 8; i++) {
        float4 wv = w4[lane + i * 32];
        float4 bv = b4[lane + i * 32];
        __half2 o0 = __floats2half2_rn((v[i].x - mu) * rstd * wv.x + bv.x,
                                       (v[i].y - mu) * rstd * wv.y + bv.y);
        __half2 o1 = __floats2half2_rn((v[i].z - mu) * rstd * wv.z + bv.z,
                                       (v[i].w - mu) * rstd * wv.w + bv.w);
        uint2 pk;
        pk.x = *(uint32_t*)&o0;
        pk.y = *(uint32_t*)&o1;
        y[lane + i * 32] = pk;
    }
}

// ---------------- layernorm (fp16 input): warp-per-row, fp32 math ----------------
__global__ void __launch_bounds__(256) lnh_kernel(const __half* __restrict__ X,
                                                  const float* __restrict__ w,
                                                  const float* __restrict__ b,
                                                  __half* __restrict__ Y) {
    int warp = threadIdx.x >> 5, lane = threadIdx.x & 31;
    int row = blockIdx.x * 8 + warp;
    const uint4* x4 = (const uint4*)(X + (size_t)row * Cc);   // 8 halves per uint4
    uint4 v[4];
    float s = 0.f, sq = 0.f;
    #pragma unroll
    for (int i = 0; i < 4; i++) {
        v[i] = x4[lane + i * 32];
        const __half2* hp = (const __half2*)&v[i];
        #pragma unroll
        for (int q = 0; q < 4; q++) {
            float2 f = __half22float2(hp[q]);
            s  += f.x + f.y;
            sq += f.x * f.x + f.y * f.y;
        }
    }
    #pragma unroll
    for (int o = 16; o > 0; o >>= 1) {
        s  += __shfl_xor_sync(0xffffffffu, s,  o);
        sq += __shfl_xor_sync(0xffffffffu, sq, o);
    }
    float mu   = s / Cc;
    float rstd = rsqrtf(sq / Cc - mu * mu + 1e-5f);
    const float2* w2 = (const float2*)w;
    const float2* b2 = (const float2*)b;
    uint4* y = (uint4*)(Y + (size_t)row * Cc);
    #pragma unroll
    for (int i = 0; i < 4; i++) {
        const __half2* hp = (const __half2*)&v[i];
        __half2 o[4];
        #pragma unroll
        for (int q = 0; q < 4; q++) {
            float2 f = __half22float2(hp[q]);
            float2 wq = w2[(lane + i * 32) * 4 + q];
            float2 bq = b2[(lane + i * 32) * 4 + q];
            o[q] = __floats2half2_rn((f.x - mu) * rstd * wq.x + bq.x,
                                     (f.y - mu) * rstd * wq.y + bq.y);
        }
        y[lane + i * 32] = *(uint4*)o;
    }
}

// ---------------- fp16 tensor-core GEMM, 4-stage cp.async ring (R9 config) ----
// C = A[M,K]@B[K,N] (+bias)(+relu)(+res fp32 | resH fp16). outH fp16 else outF fp32.
#define HG_STAGES 4
#define HG_AS (128*40)
#define HG_BS (32*136)
#define HG_SMEM (HG_STAGES*(HG_AS+HG_BS)*2)   // 75776 bytes

__global__ void __launch_bounds__(256, 2) hgemm_kernel(const __half* __restrict__ A,
                                                       const __half* __restrict__ B,
                                                       const float* __restrict__ bias,
                                                       const float* __restrict__ res,
                                                       const __half* __restrict__ resH,
                                                       float* __restrict__ outF,
                                                       __half* __restrict__ outH,
                                                       int M, int N, int K, int relu) {
    extern __shared__ __half hsm[];
    __half (*As)[128][40] = (__half(*)[128][40])hsm;
    __half (*Bs)[32][136] = (__half(*)[32][136])(hsm + HG_STAGES * HG_AS);
    int tid = threadIdx.x, lane = tid & 31, warp = tid >> 5;
    int wm = warp >> 2, wn = warp & 3;
    int m0 = blockIdx.y * 128, n0 = blockIdx.x * 128;

    float acc[4][4][4] = {};

    auto load_stage = [&](int k0, int st) {
        #pragma unroll
        for (int j = 0; j < 2; j++) {
            int idx = tid + j * 256;
            int row = idx >> 2, c = (idx & 3) * 8;
            cpa16(smem_u32(&As[st][row][c]), A + (size_t)(m0 + row) * K + k0 + c);
        }
        #pragma unroll
        for (int j = 0; j < 2; j++) {
            int idx = tid + j * 256;
            int row = idx >> 4, c = (idx & 15) * 8;
            cpa16(smem_u32(&Bs[st][row][c]), B + (size_t)(k0 + row) * N + n0 + c);
        }
    };

    int nIter = K >> 5;
    load_stage(0, 0); CP_COMMIT();
    load_stage(32, 1); CP_COMMIT();

    for (int it = 0; it < nIter; it++) {
        if (it + 2 < nIter) load_stage((it + 2) << 5, (it + 2) & 3);
        CP_COMMIT();
        CP_WAIT(2);
        __syncthreads();
        int st = it & 3;
        #pragma unroll
        for (int kk = 0; kk < 32; kk += 16) {
            uint32_t a[4][4];
            #pragma unroll
            for (int mi = 0; mi < 4; mi++)
                ldsm4(a[mi][0], a[mi][1], a[mi][2], a[mi][3],
                      smem_u32(&As[st][wm * 64 + mi * 16 + (lane & 15)][kk + (lane >> 4) * 8]));
            #pragma unroll
            for (int n2 = 0; n2 < 2; n2++) {
                uint32_t b0, b1, b2, b3;
                ldsm4t(b0, b1, b2, b3,
                       smem_u32(&Bs[st][kk + (lane & 15)][wn * 32 + n2 * 16 + (lane >> 4) * 8]));
                #pragma unroll
                for (int mi = 0; mi < 4; mi++) {
                    mma16816(acc[mi][n2 * 2],     a[mi][0], a[mi][1], a[mi][2], a[mi][3], b0, b1);
                    mma16816(acc[mi][n2 * 2 + 1], a[mi][0], a[mi][1], a[mi][2], a[mi][3], b2, b3);
                }
            }
        }
    }

    #pragma unroll
    for (int mi = 0; mi < 4; mi++) {
        #pragma unroll
        for (int ni = 0; ni < 4; ni++) {
            int col = n0 + wn * 32 + ni * 8 + (lane & 3) * 2;
            #pragma unroll
            for (int r = 0; r < 2; r++) {
                int row = m0 + wm * 64 + mi * 16 + (lane >> 2) + r * 8;
                float v0 = acc[mi][ni][r * 2], v1 = acc[mi][ni][r * 2 + 1];
                if (bias) { v0 += bias[col]; v1 += bias[col + 1]; }
                if (relu) { v0 = fmaxf(v0, 0.f); v1 = fmaxf(v1, 0.f); }
                size_t idx = (size_t)row * N + col;
                if (res)  { v0 += res[idx]; v1 += res[idx + 1]; }
                if (resH) {
                    __half2 rh = *(const __half2*)&resH[idx];
                    float2 rf = __half22float2(rh);
                    v0 += rf.x; v1 += rf.y;
                }
                if (outH) {
                    *(__half2*)&outH[idx] = __floats2half2_rn(v0, v1);
                } else {
                    *(float2*)&outF[idx] = make_float2(v0, v1);
                }
            }
        }
    }
}

// ---------------- fused flash attention, 4-stage cp.async K/V ring (R9) ----------------
#define FL_QS (128*72)
#define FL_KS (64*72)
#define FL_SMEM ((FL_QS + 8*FL_KS)*2)    // 92160 bytes

__global__ void __launch_bounds__(256, 2) flash_kernel(const __half* __restrict__ Q,
                                                       const __half* __restrict__ Kp,
                                                       const __half* __restrict__ Vp,
                                                       __half* __restrict__ Mg,
                                                       int strideQ, int pitchQ,
                                                       int strideKV, int pitchKV, int causal) {
    extern __shared__ __half fsm[];
    __half (*Qs)[72] = (__half(*)[72])fsm;
    __half (*Ks)[64][72] = (__half(*)[64][72])(fsm + FL_QS);
    __half (*Vs)[64][72] = (__half(*)[64][72])(fsm + FL_QS + 4 * FL_KS);
    int tid = threadIdx.x, lane = tid & 31, w = tid >> 5;
    int h = blockIdx.y;
    int t0 = (gridDim.x - 1 - blockIdx.x) * 128;    // heavy tiles first
    const __half* Qb = Q  + h * pitchQ;
    const __half* Kb = Kp + h * pitchKV;
    const __half* Vb = Vp + h * pitchKV;

    auto load_kv = [&](int s0, int st) {
        #pragma unroll
        for (int j = 0; j < 2; j++) {
            int idx = tid + j * 256;
            int row = idx >> 3, col = (idx & 7) * 8;
            cpa16(smem_u32(&Ks[st][row][col]), Kb + (size_t)(s0 + row) * strideKV + col);
            cpa16(smem_u32(&Vs[st][row][col]), Vb + (size_t)(s0 + row) * strideKV + col);
        }
    };

    int sEnd = causal ? (t0 + 128) : Tt;
    int nT = sEnd >> 6;
    load_kv(0, 0); CP_COMMIT();
    if (nT > 1) load_kv(64, 1);
    CP_COMMIT();

    const __half2 sc = __float2half2_rn(0.125f);
    #pragma unroll
    for (int j = 0; j < 4; j++) {
        int idx = tid + j * 256;
        int row = idx >> 3, col = (idx & 7) * 8;
        uint4 v = *(const uint4*)(Qb + (size_t)(t0 + row) * strideQ + col);
        __half2* h2 = (__half2*)&v;
        #pragma unroll
        for (int q = 0; q < 4; q++) h2[q] = __hmul2(h2[q], sc);
        *(uint4*)&Qs[row][col] = v;
    }
    __syncthreads();

    uint32_t qf[4][4];
    #pragma unroll
    for (int kk = 0; kk < 4; kk++)
        ldsm4(qf[kk][0], qf[kk][1], qf[kk][2], qf[kk][3],
              smem_u32(&Qs[w * 16 + (lane & 15)][kk * 16 + (lane >> 4) * 8]));

    float m_[2] = {-1e30f, -1e30f}, l_[2] = {0.f, 0.f};
    float acc[8][4] = {};

    for (int i = 0; i < nT; i++) {
        if (i + 2 < nT) load_kv((i + 2) << 6, (i + 2) & 3);
        CP_COMMIT();
        CP_WAIT(2);
        __syncthreads();
        int st = i & 3;
        int s0 = i << 6;

        float sacc[8][4] = {};
        #pragma unroll
        for (int kk = 0; kk < 4; kk++) {
            #pragma unroll
            for (int sg = 0; sg < 4; sg++) {
                uint32_t b0, b1, b2, b3;
                ldsm4(b0, b1, b2, b3,
                      smem_u32(&Ks[st][sg * 16 + (lane & 7) + ((lane >> 4) << 3)][kk * 16 + ((lane >> 3) & 1) * 8]));
                mma16816(sacc[sg * 2],     qf[kk][0], qf[kk][1], qf[kk][2], qf[kk][3], b0, b1);
                mma16816(sacc[sg * 2 + 1], qf[kk][0], qf[kk][1], qf[kk][2], qf[kk][3], b2, b3);
            }
        }

        if (causal && s0 + 63 > t0 + w * 16) {
            int tr0 = t0 + w * 16 + (lane >> 2);
            int tr1 = tr0 + 8;
            #pragma unroll
            for (int ni = 0; ni < 8; ni++) {
                int s = s0 + ni * 8 + (lane & 3) * 2;
                if (s > tr0)     sacc[ni][0] = -1e30f;
                if (s + 1 > tr0) sacc[ni][1] = -1e30f;
                if (s > tr1)     sacc[ni][2] = -1e30f;
                if (s + 1 > tr1) sacc[ni][3] = -1e30f;
            }
        }

        __half2 ph[8][2];
        #pragma unroll
        for (int r = 0; r < 2; r++) {
            float rm = -1e30f;
            #pragma unroll
            for (int ni = 0; ni < 8; ni++)
                rm = fmaxf(rm, fmaxf(sacc[ni][r * 2], sacc[ni][r * 2 + 1]));
            rm = fmaxf(rm, __shfl_xor_sync(0xffffffffu, rm, 1));
            rm = fmaxf(rm, __shfl_xor_sync(0xffffffffu, rm, 2));
            float mn  = fmaxf(m_[r], rm);
            float fac = __expf(m_[r] - mn);
            float ls = 0.f;
            #pragma unroll
            for (int ni = 0; ni < 8; ni++) {
                float e0 = __expf(sacc[ni][r * 2]     - mn);
                float e1 = __expf(sacc[ni][r * 2 + 1] - mn);
                ls += e0 + e1;
                ph[ni][r] = __floats2half2_rn(e0, e1);
            }
            ls += __shfl_xor_sync(0xffffffffu, ls, 1);
            ls += __shfl_xor_sync(0xffffffffu, ls, 2);
            l_[r] = l_[r] * fac + ls;
            m_[r] = mn;
            #pragma unroll
            for (int ni = 0; ni < 8; ni++) { acc[ni][r * 2] *= fac; acc[ni][r * 2 + 1] *= fac; }
        }

        #pragma unroll
        for (int kk = 0; kk < 4; kk++) {
            uint32_t a0 = *(uint32_t*)&ph[2 * kk][0];
            uint32_t a1 = *(uint32_t*)&ph[2 * kk][1];
            uint32_t a2 = *(uint32_t*)&ph[2 * kk + 1][0];
            uint32_t a3 = *(uint32_t*)&ph[2 * kk + 1][1];
            #pragma unroll
            for (int n2 = 0; n2 < 4; n2++) {
                uint32_t b0, b1, b2, b3;
                ldsm4t(b0, b1, b2, b3,
                       smem_u32(&Vs[st][kk * 16 + (lane & 15)][n2 * 16 + (lane >> 4) * 8]));
                mma16816(acc[n2 * 2],     a0, a1, a2, a3, b0, b1);
                mma16816(acc[n2 * 2 + 1], a0, a1, a2, a3, b2, b3);
            }
        }
    }

    float inv0 = 1.f / l_[0], inv1 = 1.f / l_[1];
    #pragma unroll
    for (int ni = 0; ni < 8; ni++) {
        int d = ni * 8 + (lane & 3) * 2;
        int t = t0 + w * 16 + (lane >> 2);
        *(__half2*)&Mg[(size_t)t * Cc + h * Dd + d] =
            __floats2half2_rn(acc[ni][0] * inv0, acc[ni][1] * inv0);
        *(__half2*)&Mg[(size_t)(t + 8) * Cc + h * Dd + d] =
            __floats2half2_rn(acc[ni][2] * inv1, acc[ni][3] * inv1);
    }
}

// ======================================================================
extern "C" void kernel_launch(void* const* d_in, const int* in_sizes, int n_in,
                              void* d_out, int out_size) {
    const float* x       = (const float*)d_in[0];
    const float* enc     = (const float*)d_in[1];
    const float* w_qkv   = (const float*)d_in[2];
    const float* w_proj  = (const float*)d_in[3];
    const float* b_proj  = (const float*)d_in[4];
    const float* cw_q    = (const float*)d_in[5];
    const float* cw_kv   = (const float*)d_in[6];
    const float* cw_proj = (const float*)d_in[7];
    const float* cb_proj = (const float*)d_in[8];
    const float* ff1_w1  = (const float*)d_in[9];
    const float* ff1_b1  = (const float*)d_in[10];
    const float* ff1_w2  = (const float*)d_in[11];
    const float* ff1_b2  = (const float*)d_in[12];
    const float* ff2_w1  = (const float*)d_in[13];
    const float* ff2_b1  = (const float*)d_in[14];
    const float* ff2_w2  = (const float*)d_in[15];
    const float* ff2_b2  = (const float*)d_in[16];
    const float* ln1_w = (const float*)d_in[17]; const float* ln1_b = (const float*)d_in[18];
    const float* ln2_w = (const float*)d_in[19]; const float* ln2_b = (const float*)d_in[20];
    const float* ln3_w = (const float*)d_in[21]; const float* ln3_b = (const float*)d_in[22];
    const float* ln4_w = (const float*)d_in[23]; const float* ln4_b = (const float*)d_in[24];

    __half *px, *pln, *penc, *pwqkv, *pcwq, *pcwkv, *pwproj, *pcwproj;
    __half *pf11, *pf12, *pf21, *pf22;
    __half *py, *pcq, *pkv, *pm, *pff;
    cudaGetSymbolAddress((void**)&px,     h_x);
    cudaGetSymbolAddress((void**)&pln,    h_ln);
    cudaGetSymbolAddress((void**)&penc,   h_enc);
    cudaGetSymbolAddress((void**)&pwqkv,  h_wqkv);
    cudaGetSymbolAddress((void**)&pcwq,   h_cwq);
    cudaGetSymbolAddress((void**)&pcwkv,  h_cwkv);
    cudaGetSymbolAddress((void**)&pwproj, h_wproj);
    cudaGetSymbolAddress((void**)&pcwproj,h_cwproj);
    cudaGetSymbolAddress((void**)&pf11,   h_ff1w1);
    cudaGetSymbolAddress((void**)&pf12,   h_ff1w2);
    cudaGetSymbolAddress((void**)&pf21,   h_ff2w1);
    cudaGetSymbolAddress((void**)&pf22,   h_ff2w2);
    cudaGetSymbolAddress((void**)&py,     h_y);
    cudaGetSymbolAddress((void**)&pcq,    h_cq);
    cudaGetSymbolAddress((void**)&pkv,    h_kv);
    cudaGetSymbolAddress((void**)&pm,     h_m);
    cudaGetSymbolAddress((void**)&pff,    h_ff);

    cudaFuncSetAttribute(hgemm_kernel, cudaFuncAttributeMaxDynamicSharedMemorySize, HG_SMEM);
    cudaFuncSetAttribute(flash_kernel, cudaFuncAttributeMaxDynamicSharedMemorySize, FL_SMEM);

    auto cgrid = [](int n) { return (n + 255) / 256; };

    // ---- fork root: capture-origin event BEFORE any work ----
    cudaEventRecord(g_ev0, 0);

    // ---- critical-path convert on the capture stream ----
    pack_w_kernel<<<cgrid(Hh*Cc*192/8), 256>>>(w_qkv, pwqkv, 192);
    cudaEventRecord(g_ev1, 0);               // qkv weights ready

    // ---- converts + cross-KV GEMM on side stream (joins capture via ev0) ----
    cudaStreamWaitEvent(g_s2, g_ev0, 0);
    pack_w_kernel<<<cgrid(Hh*Cc*64/8),  256, 0, g_s2>>>(cw_q,  pcwq,  64);
    pack_w_kernel<<<cgrid(Hh*Cc*128/8), 256, 0, g_s2>>>(cw_kv, pcwkv, 128);
    f2h_kernel<<<cgrid(Cc*Cc/4),  256, 0, g_s2>>>(w_proj,  pwproj,  Cc*Cc/4);
    f2h_kernel<<<cgrid(Cc*Cc/4),  256, 0, g_s2>>>(cw_proj, pcwproj, Cc*Cc/4);
    f2h_kernel<<<cgrid(Cc*FFF/4), 256, 0, g_s2>>>(ff1_w1, pf11, Cc*FFF/4);
    f2h_kernel<<<cgrid(FFF*Cc/4), 256, 0, g_s2>>>(ff1_w2, pf12, FFF*Cc/4);
    f2h_kernel<<<cgrid(Cc*FFF/4), 256, 0, g_s2>>>(ff2_w1, pf21, Cc*FFF/4);
    f2h_kernel<<<cgrid(FFF*Cc/4), 256, 0, g_s2>>>(ff2_w2, pf22, FFF*Cc/4);
    f2h_kernel<<<cgrid(MM*Cc/4),  256, 0, g_s2>>>(enc, penc, MM*Cc/4);
    cudaEventRecord(g_ev2, g_s2);            // weights ready
    hgemm_kernel<<<dim3(16, 32), 256, HG_SMEM, g_s2>>>(penc, pcwkv, nullptr, nullptr, nullptr, nullptr, pkv, MM, 2048, Cc, 0);
    cudaEventRecord(g_ev3, g_s2);            // cross K/V ready

    // ---- per-batch pipelines on 4 streams ----
    auto run_batch = [&](int b, cudaStream_t st) {
        size_t oc = (size_t)b * Tt * Cc;
        const float* pxin = x + oc;          // fp32 input slice (residual seed)
        __half* pxb  = px  + oc;             // fp16 residual stream (first write: proj1)
        __half* plnb = pln + oc;
        __half* pyb  = py  + (size_t)b * Tt * 3072;
        __half* pcqb = pcq + oc;
        __half* pkvb = pkv + (size_t)b * Tt * 2048;
        __half* pmb  = pm  + oc;
        __half* pffb = pff + (size_t)b * Tt * FFF;
        float*  poutb = (float*)d_out + oc;

        // 1) causal self-attention — ln1 reads fp32 INPUT directly
        ln_kernel<<<Tt/8, 256, 0, st>>>(pxin, ln1_w, ln1_b, plnb);
        if (st != 0) cudaStreamWaitEvent(st, g_ev1, 0);    // qkv weights ready
        hgemm_kernel<<<dim3(24, 8), 256, HG_SMEM, st>>>(plnb, pwqkv, nullptr, nullptr, nullptr, nullptr, pyb, Tt, 3072, Cc, 0);
        flash_kernel<<<dim3(8, Hh), 256, FL_SMEM, st>>>(pyb, pyb + 64, pyb + 128, pmb, 3072, 192, 3072, 192, 1);
        cudaStreamWaitEvent(st, g_ev2, 0);
        // residual seed = fp32 input; writes fp16 residual stream
        hgemm_kernel<<<dim3(8, 8), 256, HG_SMEM, st>>>(pmb, pwproj, b_proj, pxin, nullptr, nullptr, pxb, Tt, Cc, Cc, 0);

        // 2) feed-forward 1 (fp16 residual in/out)
        lnh_kernel<<<Tt/8, 256, 0, st>>>(pxb, ln2_w, ln2_b, plnb);
        hgemm_kernel<<<dim3(32, 8), 256, HG_SMEM, st>>>(plnb, pf11, ff1_b1, nullptr, nullptr, nullptr, pffb, Tt, FFF, Cc, 1);
        hgemm_kernel<<<dim3(8, 8), 256, HG_SMEM, st>>>(pffb, pf12, ff1_b2, nullptr, pxb, nullptr, pxb, Tt, Cc, FFF, 0);

        // 3) cross-attention
        lnh_kernel<<<Tt/8, 256, 0, st>>>(pxb, ln3_w, ln3_b, plnb);
        hgemm_kernel<<<dim3(8, 8), 256, HG_SMEM, st>>>(plnb, pcwq, nullptr, nullptr, nullptr, nullptr, pcqb, Tt, 1024, Cc, 0);
        cudaStreamWaitEvent(st, g_ev3, 0);
        flash_kernel<<<dim3(8, Hh), 256, FL_SMEM, st>>>(pcqb, pkvb, pkvb + 64, pmb, 1024, 64, 2048, 128, 0);
        hgemm_kernel<<<dim3(8, 8), 256, HG_SMEM, st>>>(pmb, pcwproj, cb_proj, nullptr, pxb, nullptr, pxb, Tt, Cc, Cc, 0);

        // 4) feed-forward 2 -> fp32 d_out
        lnh_kernel<<<Tt/8, 256, 0, st>>>(pxb, ln4_w, ln4_b, plnb);
        hgemm_kernel<<<dim3(32, 8), 256, HG_SMEM, st>>>(plnb, pf21, ff2_b1, nullptr, nullptr, nullptr, pffb, Tt, FFF, Cc, 1);
        hgemm_kernel<<<dim3(8, 8), 256, HG_SMEM, st>>>(pffb, pf22, ff2_b2, nullptr, pxb, poutb, nullptr, Tt, Cc, FFF, 0);
    };

    // batch streams join the capture via ev0 BEFORE any launch on them
    for (int i = 0; i < 3; i++) cudaStreamWaitEvent(g_sb[i], g_ev0, 0);
    run_batch(0, 0);
    for (int i = 0; i < 3; i++) run_batch(i + 1, g_sb[i]);

    // ---- join everything back into the capture stream ----
    for (int i = 0; i < 3; i++) {
        cudaEventRecord(g_evb[i], g_sb[i]);
        cudaStreamWaitEvent(0, g_evb[i], 0);
    }
    cudaStreamWaitEvent(0, g_ev3, 0);
}

// round 17
// speedup vs baseline: 1.1047x; 1.0042x over previous
#include <cuda_runtime.h>
#include <cuda_fp16.h>
#include <cstdint>
#include <math.h>

#define Bz  4
#define Tt  1024
#define Cc  1024
#define Hh  16
#define Dd  64
#define FFF 4096
#define MM  (Bz*Tt)           // 4096
#define NHEADS (Bz*Hh)        // 64

// ---------------- scratch (device globals) ----------------
__device__ __half h_x   [MM*Cc];                 // fp16 residual stream (first write: proj1 epilogue)
__device__ __half h_ln  [MM*Cc];
__device__ __half h_enc [MM*Cc];
__device__ __half h_wqkv[Cc*Hh*3*Dd];
__device__ __half h_cwq [Cc*Hh*Dd];
__device__ __half h_cwkv[Cc*Hh*2*Dd];
__device__ __half h_wproj[Cc*Cc];
__device__ __half h_cwproj[Cc*Cc];
__device__ __half h_ff1w1[Cc*FFF];
__device__ __half h_ff1w2[FFF*Cc];
__device__ __half h_ff2w1[Cc*FFF];
__device__ __half h_ff2w2[FFF*Cc];
__device__ __half h_y   [MM*Hh*3*Dd];            // self-attn qkv packed
__device__ __half h_cq  [MM*Cc];                 // cross-attn Q
__device__ __half h_kv  [MM*Hh*2*Dd];            // cross-attn K|V packed
__device__ __half h_m   [MM*Cc];                 // merged attention out
__device__ __half h_ff  [MM*FFF];

// ---------------- streams/events (created once, pre-main) ----------------
static cudaStream_t g_s2, g_s3, g_sb[3];
static cudaEvent_t  g_ev0, g_ev1, g_ev2, g_ev3, g_ev4, g_evb[3], g_evs3;
struct _StreamInit {
    _StreamInit() {
        cudaStreamCreateWithFlags(&g_s2, cudaStreamNonBlocking);
        cudaStreamCreateWithFlags(&g_s3, cudaStreamNonBlocking);
        for (int i = 0; i < 3; i++) cudaStreamCreateWithFlags(&g_sb[i], cudaStreamNonBlocking);
        cudaEventCreateWithFlags(&g_ev0, cudaEventDisableTiming);
        cudaEventCreateWithFlags(&g_ev1, cudaEventDisableTiming);
        cudaEventCreateWithFlags(&g_ev2, cudaEventDisableTiming);
        cudaEventCreateWithFlags(&g_ev3, cudaEventDisableTiming);
        cudaEventCreateWithFlags(&g_ev4, cudaEventDisableTiming);
        cudaEventCreateWithFlags(&g_evs3, cudaEventDisableTiming);
        for (int i = 0; i < 3; i++) cudaEventCreateWithFlags(&g_evb[i], cudaEventDisableTiming);
    }
};
static _StreamInit _stream_init_once;

// ---------------- mma/ldmatrix/cp.async helpers ----------------
__device__ __forceinline__ uint32_t smem_u32(const void* p) {
    return (uint32_t)__cvta_generic_to_shared(p);
}
__device__ __forceinline__ void ldsm4(uint32_t& r0, uint32_t& r1, uint32_t& r2, uint32_t& r3, uint32_t a) {
    asm volatile("ldmatrix.sync.aligned.m8n8.x4.shared.b16 {%0,%1,%2,%3}, [%4];"
                 : "=r"(r0), "=r"(r1), "=r"(r2), "=r"(r3) : "r"(a));
}
__device__ __forceinline__ void ldsm4t(uint32_t& r0, uint32_t& r1, uint32_t& r2, uint32_t& r3, uint32_t a) {
    asm volatile("ldmatrix.sync.aligned.m8n8.x4.trans.shared.b16 {%0,%1,%2,%3}, [%4];"
                 : "=r"(r0), "=r"(r1), "=r"(r2), "=r"(r3) : "r"(a));
}
__device__ __forceinline__ void mma16816(float* c, uint32_t a0, uint32_t a1, uint32_t a2, uint32_t a3,
                                         uint32_t b0, uint32_t b1) {
    asm volatile("mma.sync.aligned.m16n8k16.row.col.f32.f16.f16.f32 "
                 "{%0,%1,%2,%3},{%4,%5,%6,%7},{%8,%9},{%0,%1,%2,%3};"
                 : "+f"(c[0]), "+f"(c[1]), "+f"(c[2]), "+f"(c[3])
                 : "r"(a0), "r"(a1), "r"(a2), "r"(a3), "r"(b0), "r"(b1));
}
__device__ __forceinline__ void cpa16(uint32_t dst, const void* src) {
    asm volatile("cp.async.cg.shared.global [%0], [%1], 16;" :: "r"(dst), "l"(src));
}
#define CP_COMMIT()  asm volatile("cp.async.commit_group;")
#define CP_WAIT(n)   asm volatile("cp.async.wait_group %0;" :: "n"(n) : "memory")

// ---------------- converts ----------------
__global__ void f2h_kernel(const float* __restrict__ src, __half* __restrict__ dst, int n4) {
    int i = blockIdx.x * blockDim.x + threadIdx.x;
    if (i >= n4) return;
    float4 v = ((const float4*)src)[i];
    __half2* o = (__half2*)dst + i * 2;
    o[0] = __floats2half2_rn(v.x, v.y);
    o[1] = __floats2half2_rn(v.z, v.w);
}
__global__ void pack_w_kernel(const float* __restrict__ W, __half* __restrict__ Wt, int J) {
    int i = blockIdx.x * blockDim.x + threadIdx.x;
    int J8 = J >> 3;
    int total8 = Hh * Cc * J8;
    if (i >= total8) return;
    int j8 = i % J8;
    int c = (i / J8) % Cc;
    int h = i / (J8 * Cc);
    const float4* src = (const float4*)(W + (size_t)(h * Cc + c) * J + j8 * 8);
    float4 v0 = src[0], v1 = src[1];
    __half2 o[4];
    o[0] = __floats2half2_rn(v0.x, v0.y); o[1] = __floats2half2_rn(v0.z, v0.w);
    o[2] = __floats2half2_rn(v1.x, v1.y); o[3] = __floats2half2_rn(v1.z, v1.w);
    *(uint4*)(Wt + (size_t)c * (Hh * J) + h * J + j8 * 8) = *(uint4*)o;
}

// ---------------- layernorm (fp32 input): warp-per-row ----------------
__global__ void __launch_bounds__(256) ln_kernel(const float* __restrict__ X,
                                                 const float* __restrict__ w,
                                                 const float* __restrict__ b,
                                                 __half* __restrict__ Y) {
    int warp = threadIdx.x >> 5, lane = threadIdx.x & 31;
    int row = blockIdx.x * 8 + warp;
    const float4* x4 = (const float4*)(X + (size_t)row * Cc);
    float4 v[8];
    float s = 0.f, sq = 0.f;
    #pragma unroll
    for (int i = 0; i < 8; i++) {
        v[i] = x4[lane + i * 32];
        s  += v[i].x + v[i].y + v[i].z + v[i].w;
        sq += v[i].x*v[i].x + v[i].y*v[i].y + v[i].z*v[i].z + v[i].w*v[i].w;
    }
    #pragma unroll
    for (int o = 16; o > 0; o >>= 1) {
        s  += __shfl_xor_sync(0xffffffffu, s,  o);
        sq += __shfl_xor_sync(0xffffffffu, sq, o);
    }
    float mu   = s / Cc;
    float rstd = rsqrtf(sq / Cc - mu * mu + 1e-5f);
    const float4* w4 = (const float4*)w;
    const float4* b4 = (const float4*)b;
    uint2* y = (uint2*)(Y + (size_t)row * Cc);
    #pragma unroll
    for (int i = 0; i < 8; i++) {
        float4 wv = w4[lane + i * 32];
        float4 bv = b4[lane + i * 32];
        __half2 o0 = __floats2half2_rn((v[i].x - mu) * rstd * wv.x + bv.x,
                                       (v[i].y - mu) * rstd * wv.y + bv.y);
        __half2 o1 = __floats2half2_rn((v[i].z - mu) * rstd * wv.z + bv.z,
                                       (v[i].w - mu) * rstd * wv.w + bv.w);
        uint2 pk;
        pk.x = *(uint32_t*)&o0;
        pk.y = *(uint32_t*)&o1;
        y[lane + i * 32] = pk;
    }
}

// ---------------- layernorm (fp16 input): warp-per-row, fp32 math ----------------
__global__ void __launch_bounds__(256) lnh_kernel(const __half* __restrict__ X,
                                                  const float* __restrict__ w,
                                                  const float* __restrict__ b,
                                                  __half* __restrict__ Y) {
    int warp = threadIdx.x >> 5, lane = threadIdx.x & 31;
    int row = blockIdx.x * 8 + warp;
    const uint4* x4 = (const uint4*)(X + (size_t)row * Cc);   // 8 halves per uint4
    uint4 v[4];
    float s = 0.f, sq = 0.f;
    #pragma unroll
    for (int i = 0; i < 4; i++) {
        v[i] = x4[lane + i * 32];
        const __half2* hp = (const __half2*)&v[i];
        #pragma unroll
        for (int q = 0; q < 4; q++) {
            float2 f = __half22float2(hp[q]);
            s  += f.x + f.y;
            sq += f.x * f.x + f.y * f.y;
        }
    }
    #pragma unroll
    for (int o = 16; o > 0; o >>= 1) {
        s  += __shfl_xor_sync(0xffffffffu, s,  o);
        sq += __shfl_xor_sync(0xffffffffu, sq, o);
    }
    float mu   = s / Cc;
    float rstd = rsqrtf(sq / Cc - mu * mu + 1e-5f);
    const float2* w2 = (const float2*)w;
    const float2* b2 = (const float2*)b;
    uint4* y = (uint4*)(Y + (size_t)row * Cc);
    #pragma unroll
    for (int i = 0; i < 4; i++) {
        const __half2* hp = (const __half2*)&v[i];
        __half2 o[4];
        #pragma unroll
        for (int q = 0; q < 4; q++) {
            float2 f = __half22float2(hp[q]);
            float2 wq = w2[(lane + i * 32) * 4 + q];
            float2 bq = b2[(lane + i * 32) * 4 + q];
            o[q] = __floats2half2_rn((f.x - mu) * rstd * wq.x + bq.x,
                                     (f.y - mu) * rstd * wq.y + bq.y);
        }
        y[lane + i * 32] = *(uint4*)o;
    }
}

// ---------------- fp16 tensor-core GEMM, 4-stage cp.async ring (R9 config) ----
// C = A[M,K]@B[K,N] (+bias)(+relu)(+res fp32 | resH fp16). outH fp16 else outF fp32.
#define HG_STAGES 4
#define HG_AS (128*40)
#define HG_BS (32*136)
#define HG_SMEM (HG_STAGES*(HG_AS+HG_BS)*2)   // 75776 bytes

__global__ void __launch_bounds__(256, 2) hgemm_kernel(const __half* __restrict__ A,
                                                       const __half* __restrict__ B,
                                                       const float* __restrict__ bias,
                                                       const float* __restrict__ res,
                                                       const __half* __restrict__ resH,
                                                       float* __restrict__ outF,
                                                       __half* __restrict__ outH,
                                                       int M, int N, int K, int relu) {
    extern __shared__ __half hsm[];
    __half (*As)[128][40] = (__half(*)[128][40])hsm;
    __half (*Bs)[32][136] = (__half(*)[32][136])(hsm + HG_STAGES * HG_AS);
    int tid = threadIdx.x, lane = tid & 31, warp = tid >> 5;
    int wm = warp >> 2, wn = warp & 3;
    int m0 = blockIdx.y * 128, n0 = blockIdx.x * 128;

    float acc[4][4][4] = {};

    auto load_stage = [&](int k0, int st) {
        #pragma unroll
        for (int j = 0; j < 2; j++) {
            int idx = tid + j * 256;
            int row = idx >> 2, c = (idx & 3) * 8;
            cpa16(smem_u32(&As[st][row][c]), A + (size_t)(m0 + row) * K + k0 + c);
        }
        #pragma unroll
        for (int j = 0; j < 2; j++) {
            int idx = tid + j * 256;
            int row = idx >> 4, c = (idx & 15) * 8;
            cpa16(smem_u32(&Bs[st][row][c]), B + (size_t)(k0 + row) * N + n0 + c);
        }
    };

    int nIter = K >> 5;
    load_stage(0, 0); CP_COMMIT();
    load_stage(32, 1); CP_COMMIT();

    for (int it = 0; it < nIter; it++) {
        if (it + 2 < nIter) load_stage((it + 2) << 5, (it + 2) & 3);
        CP_COMMIT();
        CP_WAIT(2);
        __syncthreads();
        int st = it & 3;
        #pragma unroll
        for (int kk = 0; kk < 32; kk += 16) {
            uint32_t a[4][4];
            #pragma unroll
            for (int mi = 0; mi < 4; mi++)
                ldsm4(a[mi][0], a[mi][1], a[mi][2], a[mi][3],
                      smem_u32(&As[st][wm * 64 + mi * 16 + (lane & 15)][kk + (lane >> 4) * 8]));
            #pragma unroll
            for (int n2 = 0; n2 < 2; n2++) {
                uint32_t b0, b1, b2, b3;
                ldsm4t(b0, b1, b2, b3,
                       smem_u32(&Bs[st][kk + (lane & 15)][wn * 32 + n2 * 16 + (lane >> 4) * 8]));
                #pragma unroll
                for (int mi = 0; mi < 4; mi++) {
                    mma16816(acc[mi][n2 * 2],     a[mi][0], a[mi][1], a[mi][2], a[mi][3], b0, b1);
                    mma16816(acc[mi][n2 * 2 + 1], a[mi][0], a[mi][1], a[mi][2], a[mi][3], b2, b3);
                }
            }
        }
    }

    #pragma unroll
    for (int mi = 0; mi < 4; mi++) {
        #pragma unroll
        for (int ni = 0; ni < 4; ni++) {
            int col = n0 + wn * 32 + ni * 8 + (lane & 3) * 2;
            #pragma unroll
            for (int r = 0; r < 2; r++) {
                int row = m0 + wm * 64 + mi * 16 + (lane >> 2) + r * 8;
                float v0 = acc[mi][ni][r * 2], v1 = acc[mi][ni][r * 2 + 1];
                if (bias) { v0 += bias[col]; v1 += bias[col + 1]; }
                if (relu) { v0 = fmaxf(v0, 0.f); v1 = fmaxf(v1, 0.f); }
                size_t idx = (size_t)row * N + col;
                if (res)  { v0 += res[idx]; v1 += res[idx + 1]; }
                if (resH) {
                    __half2 rh = *(const __half2*)&resH[idx];
                    float2 rf = __half22float2(rh);
                    v0 += rf.x; v1 += rf.y;
                }
                if (outH) {
                    *(__half2*)&outH[idx] = __floats2half2_rn(v0, v1);
                } else {
                    *(float2*)&outF[idx] = make_float2(v0, v1);
                }
            }
        }
    }
}

// ---------------- fused flash attention, 4-stage cp.async K/V ring (R9) ----------------
#define FL_QS (128*72)
#define FL_KS (64*72)
#define FL_SMEM ((FL_QS + 8*FL_KS)*2)    // 92160 bytes

__global__ void __launch_bounds__(256, 2) flash_kernel(const __half* __restrict__ Q,
                                                       const __half* __restrict__ Kp,
                                                       const __half* __restrict__ Vp,
                                                       __half* __restrict__ Mg,
                                                       int strideQ, int pitchQ,
                                                       int strideKV, int pitchKV, int causal) {
    extern __shared__ __half fsm[];
    __half (*Qs)[72] = (__half(*)[72])fsm;
    __half (*Ks)[64][72] = (__half(*)[64][72])(fsm + FL_QS);
    __half (*Vs)[64][72] = (__half(*)[64][72])(fsm + FL_QS + 4 * FL_KS);
    int tid = threadIdx.x, lane = tid & 31, w = tid >> 5;
    int h = blockIdx.y;
    int t0 = (gridDim.x - 1 - blockIdx.x) * 128;    // heavy tiles first
    const __half* Qb = Q  + h * pitchQ;
    const __half* Kb = Kp + h * pitchKV;
    const __half* Vb = Vp + h * pitchKV;

    auto load_kv = [&](int s0, int st) {
        #pragma unroll
        for (int j = 0; j < 2; j++) {
            int idx = tid + j * 256;
            int row = idx >> 3, col = (idx & 7) * 8;
            cpa16(smem_u32(&Ks[st][row][col]), Kb + (size_t)(s0 + row) * strideKV + col);
            cpa16(smem_u32(&Vs[st][row][col]), Vb + (size_t)(s0 + row) * strideKV + col);
        }
    };

    int sEnd = causal ? (t0 + 128) : Tt;
    int nT = sEnd >> 6;
    load_kv(0, 0); CP_COMMIT();
    if (nT > 1) load_kv(64, 1);
    CP_COMMIT();

    const __half2 sc = __float2half2_rn(0.125f);
    #pragma unroll
    for (int j = 0; j < 4; j++) {
        int idx = tid + j * 256;
        int row = idx >> 3, col = (idx & 7) * 8;
        uint4 v = *(const uint4*)(Qb + (size_t)(t0 + row) * strideQ + col);
        __half2* h2 = (__half2*)&v;
        #pragma unroll
        for (int q = 0; q < 4; q++) h2[q] = __hmul2(h2[q], sc);
        *(uint4*)&Qs[row][col] = v;
    }
    __syncthreads();

    uint32_t qf[4][4];
    #pragma unroll
    for (int kk = 0; kk < 4; kk++)
        ldsm4(qf[kk][0], qf[kk][1], qf[kk][2], qf[kk][3],
              smem_u32(&Qs[w * 16 + (lane & 15)][kk * 16 + (lane >> 4) * 8]));

    float m_[2] = {-1e30f, -1e30f}, l_[2] = {0.f, 0.f};
    float acc[8][4] = {};

    for (int i = 0; i < nT; i++) {
        if (i + 2 < nT) load_kv((i + 2) << 6, (i + 2) & 3);
        CP_COMMIT();
        CP_WAIT(2);
        __syncthreads();
        int st = i & 3;
        int s0 = i << 6;

        float sacc[8][4] = {};
        #pragma unroll
        for (int kk = 0; kk < 4; kk++) {
            #pragma unroll
            for (int sg = 0; sg < 4; sg++) {
                uint32_t b0, b1, b2, b3;
                ldsm4(b0, b1, b2, b3,
                      smem_u32(&Ks[st][sg * 16 + (lane & 7) + ((lane >> 4) << 3)][kk * 16 + ((lane >> 3) & 1) * 8]));
                mma16816(sacc[sg * 2],     qf[kk][0], qf[kk][1], qf[kk][2], qf[kk][3], b0, b1);
                mma16816(sacc[sg * 2 + 1], qf[kk][0], qf[kk][1], qf[kk][2], qf[kk][3], b2, b3);
            }
        }

        if (causal && s0 + 63 > t0 + w * 16) {
            int tr0 = t0 + w * 16 + (lane >> 2);
            int tr1 = tr0 + 8;
            #pragma unroll
            for (int ni = 0; ni < 8; ni++) {
                int s = s0 + ni * 8 + (lane & 3) * 2;
                if (s > tr0)     sacc[ni][0] = -1e30f;
                if (s + 1 > tr0) sacc[ni][1] = -1e30f;
                if (s > tr1)     sacc[ni][2] = -1e30f;
                if (s + 1 > tr1) sacc[ni][3] = -1e30f;
            }
        }

        __half2 ph[8][2];
        #pragma unroll
        for (int r = 0; r < 2; r++) {
            float rm = -1e30f;
            #pragma unroll
            for (int ni = 0; ni < 8; ni++)
                rm = fmaxf(rm, fmaxf(sacc[ni][r * 2], sacc[ni][r * 2 + 1]));
            rm = fmaxf(rm, __shfl_xor_sync(0xffffffffu, rm, 1));
            rm = fmaxf(rm, __shfl_xor_sync(0xffffffffu, rm, 2));
            float mn  = fmaxf(m_[r], rm);
            float fac = __expf(m_[r] - mn);
            float ls = 0.f;
            #pragma unroll
            for (int ni = 0; ni < 8; ni++) {
                float e0 = __expf(sacc[ni][r * 2]     - mn);
                float e1 = __expf(sacc[ni][r * 2 + 1] - mn);
                ls += e0 + e1;
                ph[ni][r] = __floats2half2_rn(e0, e1);
            }
            ls += __shfl_xor_sync(0xffffffffu, ls, 1);
            ls += __shfl_xor_sync(0xffffffffu, ls, 2);
            l_[r] = l_[r] * fac + ls;
            m_[r] = mn;
            #pragma unroll
            for (int ni = 0; ni < 8; ni++) { acc[ni][r * 2] *= fac; acc[ni][r * 2 + 1] *= fac; }
        }

        #pragma unroll
        for (int kk = 0; kk < 4; kk++) {
            uint32_t a0 = *(uint32_t*)&ph[2 * kk][0];
            uint32_t a1 = *(uint32_t*)&ph[2 * kk][1];
            uint32_t a2 = *(uint32_t*)&ph[2 * kk + 1][0];
            uint32_t a3 = *(uint32_t*)&ph[2 * kk + 1][1];
            #pragma unroll
            for (int n2 = 0; n2 < 4; n2++) {
                uint32_t b0, b1, b2, b3;
                ldsm4t(b0, b1, b2, b3,
                       smem_u32(&Vs[st][kk * 16 + (lane & 15)][n2 * 16 + (lane >> 4) * 8]));
                mma16816(acc[n2 * 2],     a0, a1, a2, a3, b0, b1);
                mma16816(acc[n2 * 2 + 1], a0, a1, a2, a3, b2, b3);
            }
        }
    }

    float inv0 = 1.f / l_[0], inv1 = 1.f / l_[1];
    #pragma unroll
    for (int ni = 0; ni < 8; ni++) {
        int d = ni * 8 + (lane & 3) * 2;
        int t = t0 + w * 16 + (lane >> 2);
        *(__half2*)&Mg[(size_t)t * Cc + h * Dd + d] =
            __floats2half2_rn(acc[ni][0] * inv0, acc[ni][1] * inv0);
        *(__half2*)&Mg[(size_t)(t + 8) * Cc + h * Dd + d] =
            __floats2half2_rn(acc[ni][2] * inv1, acc[ni][3] * inv1);
    }
}

// ======================================================================
extern "C" void kernel_launch(void* const* d_in, const int* in_sizes, int n_in,
                              void* d_out, int out_size) {
    const float* x       = (const float*)d_in[0];
    const float* enc     = (const float*)d_in[1];
    const float* w_qkv   = (const float*)d_in[2];
    const float* w_proj  = (const float*)d_in[3];
    const float* b_proj  = (const float*)d_in[4];
    const float* cw_q    = (const float*)d_in[5];
    const float* cw_kv   = (const float*)d_in[6];
    const float* cw_proj = (const float*)d_in[7];
    const float* cb_proj = (const float*)d_in[8];
    const float* ff1_w1  = (const float*)d_in[9];
    const float* ff1_b1  = (const float*)d_in[10];
    const float* ff1_w2  = (const float*)d_in[11];
    const float* ff1_b2  = (const float*)d_in[12];
    const float* ff2_w1  = (const float*)d_in[13];
    const float* ff2_b1  = (const float*)d_in[14];
    const float* ff2_w2  = (const float*)d_in[15];
    const float* ff2_b2  = (const float*)d_in[16];
    const float* ln1_w = (const float*)d_in[17]; const float* ln1_b = (const float*)d_in[18];
    const float* ln2_w = (const float*)d_in[19]; const float* ln2_b = (const float*)d_in[20];
    const float* ln3_w = (const float*)d_in[21]; const float* ln3_b = (const float*)d_in[22];
    const float* ln4_w = (const float*)d_in[23]; const float* ln4_b = (const float*)d_in[24];

    __half *px, *pln, *penc, *pwqkv, *pcwq, *pcwkv, *pwproj, *pcwproj;
    __half *pf11, *pf12, *pf21, *pf22;
    __half *py, *pcq, *pkv, *pm, *pff;
    cudaGetSymbolAddress((void**)&px,     h_x);
    cudaGetSymbolAddress((void**)&pln,    h_ln);
    cudaGetSymbolAddress((void**)&penc,   h_enc);
    cudaGetSymbolAddress((void**)&pwqkv,  h_wqkv);
    cudaGetSymbolAddress((void**)&pcwq,   h_cwq);
    cudaGetSymbolAddress((void**)&pcwkv,  h_cwkv);
    cudaGetSymbolAddress((void**)&pwproj, h_wproj);
    cudaGetSymbolAddress((void**)&pcwproj,h_cwproj);
    cudaGetSymbolAddress((void**)&pf11,   h_ff1w1);
    cudaGetSymbolAddress((void**)&pf12,   h_ff1w2);
    cudaGetSymbolAddress((void**)&pf21,   h_ff2w1);
    cudaGetSymbolAddress((void**)&pf22,   h_ff2w2);
    cudaGetSymbolAddress((void**)&py,     h_y);
    cudaGetSymbolAddress((void**)&pcq,    h_cq);
    cudaGetSymbolAddress((void**)&pkv,    h_kv);
    cudaGetSymbolAddress((void**)&pm,     h_m);
    cudaGetSymbolAddress((void**)&pff,    h_ff);

    cudaFuncSetAttribute(hgemm_kernel, cudaFuncAttributeMaxDynamicSharedMemorySize, HG_SMEM);
    cudaFuncSetAttribute(flash_kernel, cudaFuncAttributeMaxDynamicSharedMemorySize, FL_SMEM);

    auto cgrid = [](int n) { return (n + 255) / 256; };

    // ---- fork root: capture-origin event BEFORE any work ----
    cudaEventRecord(g_ev0, 0);

    // ---- critical-path convert on the capture stream ----
    pack_w_kernel<<<cgrid(Hh*Cc*192/8), 256>>>(w_qkv, pwqkv, 192);
    cudaEventRecord(g_ev1, 0);               // qkv weights ready

    // ---- s3: cross-attention data path (cwkv, enc, KV GEMM) ----
    cudaStreamWaitEvent(g_s3, g_ev0, 0);
    pack_w_kernel<<<cgrid(Hh*Cc*128/8), 256, 0, g_s3>>>(cw_kv, pcwkv, 128);
    f2h_kernel<<<cgrid(MM*Cc/4),  256, 0, g_s3>>>(enc, penc, MM*Cc/4);
    hgemm_kernel<<<dim3(16, 32), 256, HG_SMEM, g_s3>>>(penc, pcwkv, nullptr, nullptr, nullptr, nullptr, pkv, MM, 2048, Cc, 0);
    cudaEventRecord(g_ev3, g_s3);            // cross K/V ready (early)

    // ---- s2: weight converts ordered by first use ----
    cudaStreamWaitEvent(g_s2, g_ev0, 0);
    pack_w_kernel<<<cgrid(Hh*Cc*64/8),  256, 0, g_s2>>>(cw_q,  pcwq,  64);
    f2h_kernel<<<cgrid(Cc*Cc/4),  256, 0, g_s2>>>(w_proj,  pwproj,  Cc*Cc/4);
    f2h_kernel<<<cgrid(Cc*FFF/4), 256, 0, g_s2>>>(ff1_w1, pf11, Cc*FFF/4);
    f2h_kernel<<<cgrid(FFF*Cc/4), 256, 0, g_s2>>>(ff1_w2, pf12, FFF*Cc/4);
    cudaEventRecord(g_ev2, g_s2);            // wproj + ff1 weights + cwq ready (early)
    f2h_kernel<<<cgrid(Cc*Cc/4),  256, 0, g_s2>>>(cw_proj, pcwproj, Cc*Cc/4);
    f2h_kernel<<<cgrid(Cc*FFF/4), 256, 0, g_s2>>>(ff2_w1, pf21, Cc*FFF/4);
    f2h_kernel<<<cgrid(FFF*Cc/4), 256, 0, g_s2>>>(ff2_w2, pf22, FFF*Cc/4);
    cudaEventRecord(g_ev4, g_s2);            // cwproj + ff2 weights ready

    // ---- per-batch pipelines on 4 streams ----
    auto run_batch = [&](int b, cudaStream_t st) {
        size_t oc = (size_t)b * Tt * Cc;
        const float* pxin = x + oc;          // fp32 input slice (residual seed)
        __half* pxb  = px  + oc;             // fp16 residual stream (first write: proj1)
        __half* plnb = pln + oc;
        __half* pyb  = py  + (size_t)b * Tt * 3072;
        __half* pcqb = pcq + oc;
        __half* pkvb = pkv + (size_t)b * Tt * 2048;
        __half* pmb  = pm  + oc;
        __half* pffb = pff + (size_t)b * Tt * FFF;
        float*  poutb = (float*)d_out + oc;

        // 1) causal self-attention — ln1 reads fp32 INPUT directly
        ln_kernel<<<Tt/8, 256, 0, st>>>(pxin, ln1_w, ln1_b, plnb);
        if (st != 0) cudaStreamWaitEvent(st, g_ev1, 0);    // qkv weights ready
        hgemm_kernel<<<dim3(24, 8), 256, HG_SMEM, st>>>(plnb, pwqkv, nullptr, nullptr, nullptr, nullptr, pyb, Tt, 3072, Cc, 0);
        flash_kernel<<<dim3(8, Hh), 256, FL_SMEM, st>>>(pyb, pyb + 64, pyb + 128, pmb, 3072, 192, 3072, 192, 1);
        cudaStreamWaitEvent(st, g_ev2, 0);   // wproj/ff1/cwq ready
        // residual seed = fp32 input; writes fp16 residual stream
        hgemm_kernel<<<dim3(8, 8), 256, HG_SMEM, st>>>(pmb, pwproj, b_proj, pxin, nullptr, nullptr, pxb, Tt, Cc, Cc, 0);

        // 2) feed-forward 1 (fp16 residual in/out)
        lnh_kernel<<<Tt/8, 256, 0, st>>>(pxb, ln2_w, ln2_b, plnb);
        hgemm_kernel<<<dim3(32, 8), 256, HG_SMEM, st>>>(plnb, pf11, ff1_b1, nullptr, nullptr, nullptr, pffb, Tt, FFF, Cc, 1);
        hgemm_kernel<<<dim3(8, 8), 256, HG_SMEM, st>>>(pffb, pf12, ff1_b2, nullptr, pxb, nullptr, pxb, Tt, Cc, FFF, 0);

        // 3) cross-attention
        lnh_kernel<<<Tt/8, 256, 0, st>>>(pxb, ln3_w, ln3_b, plnb);
        hgemm_kernel<<<dim3(8, 8), 256, HG_SMEM, st>>>(plnb, pcwq, nullptr, nullptr, nullptr, nullptr, pcqb, Tt, 1024, Cc, 0);
        cudaStreamWaitEvent(st, g_ev3, 0);   // cross K/V ready
        flash_kernel<<<dim3(8, Hh), 256, FL_SMEM, st>>>(pcqb, pkvb, pkvb + 64, pmb, 1024, 64, 2048, 128, 0);
        cudaStreamWaitEvent(st, g_ev4, 0);   // cwproj + ff2 weights ready
        hgemm_kernel<<<dim3(8, 8), 256, HG_SMEM, st>>>(pmb, pcwproj, cb_proj, nullptr, pxb, nullptr, pxb, Tt, Cc, Cc, 0);

        // 4) feed-forward 2 -> fp32 d_out
        lnh_kernel<<<Tt/8, 256, 0, st>>>(pxb, ln4_w, ln4_b, plnb);
        hgemm_kernel<<<dim3(32, 8), 256, HG_SMEM, st>>>(plnb, pf21, ff2_b1, nullptr, nullptr, nullptr, pffb, Tt, FFF, Cc, 1);
        hgemm_kernel<<<dim3(8, 8), 256, HG_SMEM, st>>>(pffb, pf22, ff2_b2, nullptr, pxb, poutb, nullptr, Tt, Cc, FFF, 0);
    };

    // batch streams join the capture via ev0 BEFORE any launch on them
    for (int i = 0; i < 3; i++) cudaStreamWaitEvent(g_sb[i], g_ev0, 0);
    run_batch(0, 0);
    for (int i = 0; i < 3; i++) run_batch(i + 1, g_sb[i]);

    // ---- join everything back into the capture stream ----
    for (int i = 0; i < 3; i++) {
        cudaEventRecord(g_evb[i], g_sb[i]);
        cudaStreamWaitEvent(0, g_evb[i], 0);
    }
    cudaEventRecord(g_evs3, g_s3);
    cudaStreamWaitEvent(0, g_evs3, 0);
    cudaStreamWaitEvent(0, g_ev4, 0);
}